// round 2
// baseline (speedup 1.0000x reference)
#include <cuda_runtime.h>
#include <math.h>

#define BB   8
#define CIN  256
#define LIN  2046
#define LPAD 2048
#define IC   64
#define OCH  128
#define BNEPS 1e-5f

// ---------------- scratch ----------------
__device__ float g_pre1[BB*IC*LPAD];
__device__ float g_pre2[BB*IC*LPAD];
__device__ float g_preA[BB*IC*LPAD];
__device__ float g_preB[BB*IC*LPAD];
__device__ float g_feat1[BB*IC*LPAD];
__device__ float g_feat2[BB*IC*LPAD];
__device__ float g_saconv[BB*IC*LPAD];
__device__ float g_scconv[BB*IC*LPAD];
__device__ float g_safeat[BB*IC*LPAD];
__device__ float g_scfeat[BB*IC*LPAD];
__device__ float g_qk[BB*LPAD*16];
__device__ float g_v[BB*IC*LPAD];
__device__ float g_rowM[BB*LPAD];
__device__ float g_rowI[BB*LPAD];
__device__ float g_came[BB*IC*IC];
__device__ float g_camattn[BB*IC*IC];
__device__ float g_msum[BB*IC];
__device__ float g_mu[4*IC];
__device__ float g_rs[4*IC];

__device__ __forceinline__ float* selbuf(int s) {
    switch (s) {
        case 0: return g_pre1;   case 1: return g_pre2;
        case 2: return g_preA;   case 3: return g_preB;
        case 4: return g_feat1;  case 5: return g_feat2;
        case 6: return g_saconv; case 7: return g_scconv;
        case 8: return g_safeat; default: return g_scfeat;
    }
}

// ---------- conv1x1 from x (256 -> 128 combined outs), write at l+1 ----------
__global__ __launch_bounds__(256) void k_convx(const float* __restrict__ x,
                                               const float* __restrict__ W5a,
                                               const float* __restrict__ W5c) {
    int b = blockIdx.z, o0 = blockIdx.y * 64, l0 = blockIdx.x * 64;
    __shared__ float Ws[16][65], Xs[16][65];
    int tid = threadIdx.x, ty = tid / 16, tx = tid % 16;
    float acc[4][4] = {};
    const float* xb = x + (size_t)b * CIN * LIN;
    for (int kc = 0; kc < CIN; kc += 16) {
#pragma unroll
        for (int t = 0; t < 4; t++) {
            int i = tid + t * 256, k = i / 64, o = i % 64;
            int oo = o0 + o;
            const float* Wp = (oo < IC) ? (W5a + oo * CIN) : (W5c + (oo - IC) * CIN);
            Ws[k][o] = Wp[kc + k];
        }
#pragma unroll
        for (int t = 0; t < 4; t++) {
            int i = tid + t * 256, k = i / 64, l = i % 64;
            int gl = l0 + l;
            Xs[k][l] = (gl < LIN) ? xb[(size_t)(kc + k) * LIN + gl] : 0.f;
        }
        __syncthreads();
#pragma unroll
        for (int k = 0; k < 16; k++) {
            float a[4], bv[4];
#pragma unroll
            for (int i = 0; i < 4; i++) a[i] = Ws[k][ty * 4 + i];
#pragma unroll
            for (int j = 0; j < 4; j++) bv[j] = Xs[k][tx * 4 + j];
#pragma unroll
            for (int i = 0; i < 4; i++)
#pragma unroll
                for (int j = 0; j < 4; j++) acc[i][j] += a[i] * bv[j];
        }
        __syncthreads();
    }
#pragma unroll
    for (int i = 0; i < 4; i++) {
        int o = o0 + ty * 4 + i;
        float* dst = (o < IC) ? (g_pre1 + ((size_t)b * IC + o) * LPAD)
                              : (g_pre2 + ((size_t)b * IC + (o - IC)) * LPAD);
#pragma unroll
        for (int j = 0; j < 4; j++) {
            int l = l0 + tx * 4 + j;
            if (l < LIN) dst[l + 1] = acc[i][j];
        }
    }
}

// ---------- BN stats over (B, full padded L); border==0 handled by flag ----------
__global__ void k_stats(int sel, int slot, int border) {
    const float* pre = selbuf(sel);
    int ch = blockIdx.x;
    int lo = border ? 1 : 0;
    int cnt = border ? (LPAD - 2) : LPAD;
    float s = 0.f, ss = 0.f;
    for (int i = threadIdx.x; i < BB * cnt; i += 256) {
        int b = i / cnt, l = lo + i % cnt;
        float v = pre[((size_t)b * IC + ch) * LPAD + l];
        s += v; ss += v * v;
    }
    __shared__ float r1[256], r2[256];
    r1[threadIdx.x] = s; r2[threadIdx.x] = ss; __syncthreads();
    for (int st = 128; st > 0; st >>= 1) {
        if (threadIdx.x < st) { r1[threadIdx.x] += r1[threadIdx.x + st]; r2[threadIdx.x] += r2[threadIdx.x + st]; }
        __syncthreads();
    }
    if (threadIdx.x == 0) {
        float N = (float)(BB * LPAD);
        float mu = r1[0] / N;
        float var = r2[0] / N - mu * mu;
        g_mu[slot * IC + ch] = mu;
        g_rs[slot * IC + ch] = rsqrtf(var + BNEPS);
    }
}

__global__ void k_bnrelu(int psel, int osel, const float* __restrict__ g,
                         const float* __restrict__ bia, int slot, int border) {
    const float* pre = selbuf(psel);
    float* out = selbuf(osel);
    int idx = blockIdx.x * 256 + threadIdx.x;
    int l = idx & (LPAD - 1);
    int c = (idx >> 11) & (IC - 1);
    float v = pre[idx];
    if (border && (l == 0 || l == LPAD - 1)) v = 0.f;
    float y = (v - g_mu[slot * IC + c]) * g_rs[slot * IC + c] * g[c] + bia[c];
    out[idx] = fmaxf(y, 0.f);
}

// ---------- q/k/v from feat1 (80 outputs) ----------
__global__ __launch_bounds__(256) void k_qkv(const float* __restrict__ Wq, const float* __restrict__ bq,
                                             const float* __restrict__ Wk, const float* __restrict__ bk,
                                             const float* __restrict__ Wv, const float* __restrict__ bvw) {
    int b = blockIdx.y, l0 = blockIdx.x * 64;
    __shared__ float Wsm[80][65], Fs[64][65];
    int tid = threadIdx.x;
    for (int i = tid; i < 80 * 64; i += 256) {
        int o = i / 64, k = i % 64;
        float v;
        if (o < 8)       v = Wq[o * IC + k];
        else if (o < 16) v = Wk[(o - 8) * IC + k];
        else             v = Wv[(o - 16) * IC + k];
        Wsm[o][k] = v;
    }
    const float* f1 = g_feat1 + (size_t)b * IC * LPAD;
    for (int i = tid; i < 64 * 64; i += 256) {
        int k = i / 64, l = i % 64;
        Fs[k][l] = f1[(size_t)k * LPAD + l0 + l];
    }
    __syncthreads();
    int l = tid % 64, ob = tid / 64;   // 20 o's: ob + t*4
    float acc[20] = {};
#pragma unroll 8
    for (int k = 0; k < 64; k++) {
        float fl = Fs[k][l];
#pragma unroll
        for (int t = 0; t < 20; t++) acc[t] += Wsm[ob + t * 4][k] * fl;
    }
#pragma unroll
    for (int t = 0; t < 20; t++) {
        int o = ob + t * 4;
        float bias = (o < 8) ? bq[o] : ((o < 16) ? bk[o - 8] : bvw[o - 16]);
        float val = acc[t] + bias;
        if (o < 16) g_qk[((size_t)b * LPAD + l0 + l) * 16 + o] = val;
        else        g_v[((size_t)b * IC + (o - 16)) * LPAD + l0 + l] = val;
    }
}

// ---------- per-row softmax stats (max, 1/sum) ----------
__global__ void k_rowstats() {
    int b = blockIdx.y;
    int l = blockIdx.x * 8 + threadIdx.y;
    int lane = threadIdx.x;
    const float4* qp = (const float4*)(g_qk + ((size_t)b * LPAD + l) * 16);
    float4 q0 = qp[0], q1 = qp[1];
    float mx = -1e30f, sm = 0.f;
    for (int m = lane; m < LPAD; m += 32) {
        const float4* kp = (const float4*)(g_qk + ((size_t)b * LPAD + m) * 16 + 8);
        float4 k0 = kp[0], k1 = kp[1];
        float s = q0.x * k0.x + q0.y * k0.y + q0.z * k0.z + q0.w * k0.w
                + q1.x * k1.x + q1.y * k1.y + q1.z * k1.z + q1.w * k1.w;
        if (s <= mx) sm += __expf(s - mx);
        else { sm = sm * __expf(mx - s) + 1.f; mx = s; }
    }
#pragma unroll
    for (int off = 16; off > 0; off >>= 1) {
        float om = __shfl_xor_sync(0xffffffffu, mx, off);
        float os = __shfl_xor_sync(0xffffffffu, sm, off);
        float nm = fmaxf(mx, om);
        sm = sm * __expf(mx - nm) + os * __expf(om - nm);
        mx = nm;
    }
    if (lane == 0) { g_rowM[b * LPAD + l] = mx; g_rowI[b * LPAD + l] = 1.f / sm; }
}

// ---------- PAM: recompute scores, softmax-normalize, V-accumulate, epilogue ----------
__global__ __launch_bounds__(256) void k_pamout(const float* __restrict__ gamma) {
    int b = blockIdx.y, l0 = blockIdx.x * 64;
    __shared__ float qsm[64][9], ks[8][65], vs[64][65], ps[64][65];
    __shared__ float Ms[64], Is[64];
    int tid = threadIdx.x;
    for (int i = tid; i < 64 * 8; i += 256) {
        int l = i / 8, j = i % 8;
        qsm[l][j] = g_qk[((size_t)b * LPAD + l0 + l) * 16 + j];
    }
    if (tid < 64) { Ms[tid] = g_rowM[b * LPAD + l0 + tid]; Is[tid] = g_rowI[b * LPAD + l0 + tid]; }
    __syncthreads();
    int lq = tid % 64, mq = (tid / 64) * 16;
    float qr[8];
#pragma unroll
    for (int j = 0; j < 8; j++) qr[j] = qsm[lq][j];
    float Mv = Ms[lq], Iv = Is[lq];
    int cy = (tid / 16) * 4, lx = (tid % 16) * 4;
    float acc[4][4] = {};
    for (int m0 = 0; m0 < LPAD; m0 += 64) {
        for (int i = tid; i < 512; i += 256) {
            int j = i / 64, m = i % 64;
            ks[j][m] = g_qk[((size_t)b * LPAD + m0 + m) * 16 + 8 + j];
        }
        for (int i = tid; i < 4096; i += 256) {
            int c = i / 64, m = i % 64;
            vs[c][m] = g_v[((size_t)b * IC + c) * LPAD + m0 + m];
        }
        __syncthreads();
#pragma unroll
        for (int t = 0; t < 16; t++) {
            int m = mq + t;
            float s = 0.f;
#pragma unroll
            for (int j = 0; j < 8; j++) s += qr[j] * ks[j][m];
            ps[lq][m] = __expf(s - Mv) * Iv;
        }
        __syncthreads();
#pragma unroll 8
        for (int m = 0; m < 64; m++) {
            float pv[4], vv[4];
#pragma unroll
            for (int j = 0; j < 4; j++) pv[j] = ps[lx + j][m];
#pragma unroll
            for (int i = 0; i < 4; i++) vv[i] = vs[cy + i][m];
#pragma unroll
            for (int i = 0; i < 4; i++)
#pragma unroll
                for (int j = 0; j < 4; j++) acc[i][j] += vv[i] * pv[j];
        }
        __syncthreads();
    }
    float gm = gamma[0];
#pragma unroll
    for (int i = 0; i < 4; i++)
#pragma unroll
        for (int j = 0; j < 4; j++) {
            size_t idx = ((size_t)b * IC + cy + i) * LPAD + l0 + lx + j;
            g_safeat[idx] = gm * acc[i][j] + g_feat1[idx];
        }
}

// ---------- CAM ----------
__global__ void k_zero() {
    int idx = blockIdx.x * 256 + threadIdx.x;
    if (idx < BB * IC * IC) g_came[idx] = 0.f;
}

__global__ __launch_bounds__(256) void k_came() {
    int b = blockIdx.x, ls = blockIdx.y;
    __shared__ float Fs[64][33];
    int tid = threadIdx.x;
    int cy = (tid / 16) * 4, dx = (tid % 16) * 4;
    float acc[4][4] = {};
    const float* f2 = g_feat2 + (size_t)b * IC * LPAD;
    for (int lt = 0; lt < 4; lt++) {
        int l0 = ls * 128 + lt * 32;
        for (int i = tid; i < 64 * 32; i += 256) {
            int c = i / 32, j = i % 32;
            Fs[c][j] = f2[(size_t)c * LPAD + l0 + j];
        }
        __syncthreads();
#pragma unroll 8
        for (int j = 0; j < 32; j++) {
            float a[4], bv[4];
#pragma unroll
            for (int i = 0; i < 4; i++) a[i] = Fs[cy + i][j];
#pragma unroll
            for (int i = 0; i < 4; i++) bv[i] = Fs[dx + i][j];
#pragma unroll
            for (int i = 0; i < 4; i++)
#pragma unroll
                for (int jj = 0; jj < 4; jj++) acc[i][jj] += a[i] * bv[jj];
        }
        __syncthreads();
    }
#pragma unroll
    for (int i = 0; i < 4; i++)
#pragma unroll
        for (int jj = 0; jj < 4; jj++)
            atomicAdd(&g_came[b * 4096 + (cy + i) * 64 + dx + jj], acc[i][jj]);
}

__global__ void k_camsm() {
    int b = blockIdx.x >> 6, c = blockIdx.x & 63;
    int t = threadIdx.x;
    __shared__ float red[64];
    float e = g_came[b * 4096 + c * 64 + t];
    red[t] = e; __syncthreads();
    for (int st = 32; st > 0; st >>= 1) { if (t < st) red[t] = fmaxf(red[t], red[t + st]); __syncthreads(); }
    float rmax = red[0]; __syncthreads();
    float v = rmax - e;
    red[t] = v; __syncthreads();
    for (int st = 32; st > 0; st >>= 1) { if (t < st) red[t] = fmaxf(red[t], red[t + st]); __syncthreads(); }
    float vm = red[0]; __syncthreads();
    float p = __expf(v - vm);
    red[t] = p; __syncthreads();
    for (int st = 32; st > 0; st >>= 1) { if (t < st) red[t] += red[t + st]; __syncthreads(); }
    g_camattn[b * 4096 + c * 64 + t] = p / red[0];
}

__global__ __launch_bounds__(256) void k_camout(const float* __restrict__ gamma) {
    int b = blockIdx.y, l0 = blockIdx.x * 64;
    __shared__ float As[64][65], Fs[64][65];
    int tid = threadIdx.x;
    const float* f2 = g_feat2 + (size_t)b * IC * LPAD;
    for (int i = tid; i < 4096; i += 256) As[i / 64][i % 64] = g_camattn[b * 4096 + i];
    for (int i = tid; i < 4096; i += 256) {
        int d = i / 64, l = i % 64;
        Fs[d][l] = f2[(size_t)d * LPAD + l0 + l];
    }
    __syncthreads();
    int cy = (tid / 16) * 4, lx = (tid % 16) * 4;
    float acc[4][4] = {};
#pragma unroll 8
    for (int d = 0; d < 64; d++) {
        float a[4], bv[4];
#pragma unroll
        for (int i = 0; i < 4; i++) a[i] = As[cy + i][d];
#pragma unroll
        for (int j = 0; j < 4; j++) bv[j] = Fs[d][lx + j];
#pragma unroll
        for (int i = 0; i < 4; i++)
#pragma unroll
            for (int j = 0; j < 4; j++) acc[i][j] += a[i] * bv[j];
    }
    float gm = gamma[0];
#pragma unroll
    for (int i = 0; i < 4; i++)
#pragma unroll
        for (int j = 0; j < 4; j++) {
            size_t idx = ((size_t)b * IC + cy + i) * LPAD + l0 + lx + j;
            g_scfeat[idx] = gm * acc[i][j] + f2[(size_t)(cy + i) * LPAD + l0 + lx + j];
        }
}

// ---------- conv3 pad1 (64 -> 64) ----------
__global__ __launch_bounds__(256) void k_conv3(int fsel, const float* __restrict__ W, int osel) {
    const float* f = selbuf(fsel);
    float* out = selbuf(osel);
    int b = blockIdx.y, l0 = blockIdx.x * 128;
    __shared__ float Fs[16][134], Ws2[16][194];
    int tid = threadIdx.x;
    int og = tid / 32, lg = tid % 32;
    float acc[8][4] = {};
    const float* fb = f + (size_t)b * IC * LPAD;
    for (int c0 = 0; c0 < 64; c0 += 16) {
        for (int i = tid; i < 2080; i += 256) {
            int cc = i / 130, j = i % 130;
            int gl = l0 + j - 1;
            Fs[cc][j] = (gl >= 0 && gl < LPAD) ? fb[(size_t)(c0 + cc) * LPAD + gl] : 0.f;
        }
        for (int i = tid; i < 3072; i += 256) {
            int o = i / 48, r = i % 48;
            Ws2[r / 3][o * 3 + (r % 3)] = W[o * 192 + c0 * 3 + r];
        }
        __syncthreads();
#pragma unroll
        for (int cc = 0; cc < 16; cc++) {
            float bv[7];
#pragma unroll
            for (int j = 0; j < 7; j++) bv[j] = Fs[cc][lg * 4 + j];
#pragma unroll
            for (int oi = 0; oi < 8; oi++) {
                int o = og * 8 + oi;
                float w0 = Ws2[cc][o * 3], w1 = Ws2[cc][o * 3 + 1], w2 = Ws2[cc][o * 3 + 2];
#pragma unroll
                for (int lj = 0; lj < 4; lj++)
                    acc[oi][lj] += w0 * bv[lj] + w1 * bv[lj + 1] + w2 * bv[lj + 2];
            }
        }
        __syncthreads();
    }
#pragma unroll
    for (int oi = 0; oi < 8; oi++)
#pragma unroll
        for (int lj = 0; lj < 4; lj++)
            out[((size_t)b * IC + og * 8 + oi) * LPAD + l0 + lg * 4 + lj] = acc[oi][lj];
}

// ---------- final 1x1 conv 64 -> 128 with bias ----------
__global__ __launch_bounds__(256) void k_out1x1(int ssel, const float* __restrict__ W,
                                                const float* __restrict__ bias,
                                                float* __restrict__ dst) {
    const float* src = selbuf(ssel);
    int b = blockIdx.z, o0 = blockIdx.y * 64, l0 = blockIdx.x * 64;
    __shared__ float Ws[16][65], Xs[16][65];
    int tid = threadIdx.x, ty = tid / 16, tx = tid % 16;
    float acc[4][4] = {};
    const float* sb = src + (size_t)b * IC * LPAD;
    for (int kc = 0; kc < 64; kc += 16) {
#pragma unroll
        for (int t = 0; t < 4; t++) {
            int i = tid + t * 256, k = i / 64, o = i % 64;
            Ws[k][o] = W[(o0 + o) * 64 + kc + k];
        }
#pragma unroll
        for (int t = 0; t < 4; t++) {
            int i = tid + t * 256, k = i / 64, l = i % 64;
            Xs[k][l] = sb[(size_t)(kc + k) * LPAD + l0 + l];
        }
        __syncthreads();
#pragma unroll
        for (int k = 0; k < 16; k++) {
            float a[4], bv[4];
#pragma unroll
            for (int i = 0; i < 4; i++) a[i] = Ws[k][ty * 4 + i];
#pragma unroll
            for (int j = 0; j < 4; j++) bv[j] = Xs[k][tx * 4 + j];
#pragma unroll
            for (int i = 0; i < 4; i++)
#pragma unroll
                for (int j = 0; j < 4; j++) acc[i][j] += a[i] * bv[j];
        }
        __syncthreads();
    }
#pragma unroll
    for (int i = 0; i < 4; i++) {
        int o = o0 + ty * 4 + i;
        float bs = bias[o];
#pragma unroll
        for (int j = 0; j < 4; j++)
            dst[((size_t)b * OCH + o) * LPAD + l0 + tx * 4 + j] = acc[i][j] + bs;
    }
}

// ---------- column mean of (saconv + scconv) ----------
__global__ void k_colmean() {
    int b = blockIdx.x / IC, c = blockIdx.x % IC;
    const float* p1 = g_saconv + ((size_t)b * IC + c) * LPAD;
    const float* p2 = g_scconv + ((size_t)b * IC + c) * LPAD;
    float s = 0.f;
    for (int l = threadIdx.x; l < LPAD; l += 256) s += p1[l] + p2[l];
    __shared__ float red[256];
    red[threadIdx.x] = s; __syncthreads();
    for (int st = 128; st > 0; st >>= 1) {
        if (threadIdx.x < st) red[threadIdx.x] += red[threadIdx.x + st];
        __syncthreads();
    }
    if (threadIdx.x == 0) g_msum[b * IC + c] = red[0] / (float)LPAD;
}

__global__ void k_sasc(const float* __restrict__ W8, const float* __restrict__ b8,
                       float* __restrict__ dout) {
    int b = blockIdx.x, o = threadIdx.x;
    float s = b8[o];
    for (int c = 0; c < IC; c++) s += W8[o * IC + c] * g_msum[b * IC + c];
    dout[b * OCH + o] = s;
}

extern "C" void kernel_launch(void* const* d_in, const int* in_sizes, int n_in,
                              void* d_out, int out_size) {
    const float* x   = (const float*)d_in[0];
    const float* W5a = (const float*)d_in[1];
    const float* g5a = (const float*)d_in[2];
    const float* b5a = (const float*)d_in[3];
    const float* W5c = (const float*)d_in[4];
    const float* g5c = (const float*)d_in[5];
    const float* b5c = (const float*)d_in[6];
    const float* Wq  = (const float*)d_in[7];
    const float* bq  = (const float*)d_in[8];
    const float* Wk  = (const float*)d_in[9];
    const float* bk  = (const float*)d_in[10];
    const float* Wv  = (const float*)d_in[11];
    const float* bv  = (const float*)d_in[12];
    const float* gpam = (const float*)d_in[13];
    const float* gcam = (const float*)d_in[14];
    const float* W51 = (const float*)d_in[15];
    const float* g51 = (const float*)d_in[16];
    const float* b51 = (const float*)d_in[17];
    const float* W52 = (const float*)d_in[18];
    const float* g52 = (const float*)d_in[19];
    const float* b52 = (const float*)d_in[20];
    const float* W6  = (const float*)d_in[21];
    const float* b6  = (const float*)d_in[22];
    const float* W7  = (const float*)d_in[23];
    const float* b7  = (const float*)d_in[24];
    const float* W8  = (const float*)d_in[25];
    const float* b8  = (const float*)d_in[26];
    float* out = (float*)d_out;
    const size_t OUTSZ = (size_t)BB * OCH * LPAD;   // 2097152

    k_convx<<<dim3(32, 2, BB), 256>>>(x, W5a, W5c);
    k_stats<<<IC, 256>>>(0, 0, 1);
    k_stats<<<IC, 256>>>(1, 1, 1);
    k_bnrelu<<<4096, 256>>>(0, 4, g5a, b5a, 0, 1);
    k_bnrelu<<<4096, 256>>>(1, 5, g5c, b5c, 1, 1);

    // PAM branch
    k_qkv<<<dim3(32, BB), 256>>>(Wq, bq, Wk, bk, Wv, bv);
    k_rowstats<<<dim3(256, BB), dim3(32, 8)>>>();
    k_pamout<<<dim3(32, BB), 256>>>(gpam);
    k_conv3<<<dim3(16, BB), 256>>>(8, W51, 2);
    k_stats<<<IC, 256>>>(2, 2, 0);
    k_bnrelu<<<4096, 256>>>(2, 6, g51, b51, 2, 0);
    k_out1x1<<<dim3(32, 2, BB), 256>>>(6, W6, b6, out + BB * OCH);

    // CAM branch
    k_zero<<<128, 256>>>();
    k_came<<<dim3(BB, 16), 256>>>();
    k_camsm<<<BB * IC, 64>>>();
    k_camout<<<dim3(32, BB), 256>>>(gcam);
    k_conv3<<<dim3(16, BB), 256>>>(9, W52, 3);
    k_stats<<<IC, 256>>>(3, 3, 0);
    k_bnrelu<<<4096, 256>>>(3, 7, g52, b52, 3, 0);
    k_out1x1<<<dim3(32, 2, BB), 256>>>(7, W7, b7, out + BB * OCH + OUTSZ);

    // fused mean path: mean(conv1x1(sum)) == W8 @ mean(sum) + b8
    k_colmean<<<BB * IC, 256>>>();
    k_sasc<<<BB, OCH>>>(W8, b8, out);
}

// round 4
// speedup vs baseline: 1.0761x; 1.0761x over previous
#include <cuda_runtime.h>
#include <math.h>

#define BB   8
#define CIN  256
#define LIN  2046
#define LPAD 2048
#define IC   64
#define OCH  128
#define BNEPS 1e-5f

typedef unsigned long long u64;
__device__ __forceinline__ u64 pk2(float x, float y) { u64 r; asm("mov.b64 %0,{%1,%2};" : "=l"(r) : "f"(x), "f"(y)); return r; }
__device__ __forceinline__ float2 up2(u64 v) { float2 r; asm("mov.b64 {%0,%1},%2;" : "=f"(r.x), "=f"(r.y) : "l"(v)); return r; }
__device__ __forceinline__ void fma2(u64& d, u64 a, u64 b) { asm("fma.rn.f32x2 %0,%1,%2,%0;" : "+l"(d) : "l"(a), "l"(b)); }

// ---------------- scratch ----------------
__device__ float g_pre1[BB*IC*LPAD];
__device__ float g_pre2[BB*IC*LPAD];
__device__ float g_preA[BB*IC*LPAD];
__device__ float g_preB[BB*IC*LPAD];
__device__ float g_feat1[BB*IC*LPAD];
__device__ float g_feat2[BB*IC*LPAD];
__device__ float g_saconv[BB*IC*LPAD];
__device__ float g_scconv[BB*IC*LPAD];
__device__ float g_safeat[BB*IC*LPAD];
__device__ float g_scfeat[BB*IC*LPAD];
__device__ float g_qk[BB*LPAD*16];
__device__ float g_v[BB*IC*LPAD];
__device__ float g_rowM[BB*LPAD];
__device__ float g_rowI[BB*LPAD];
__device__ float g_came[BB*IC*IC];
__device__ float g_camattn[BB*IC*IC];
__device__ float g_msum[BB*IC];
__device__ float g_sS[4*IC];
__device__ float g_sSS[4*IC];

__device__ __forceinline__ float* selbuf(int s) {
    switch (s) {
        case 0: return g_pre1;   case 1: return g_pre2;
        case 2: return g_preA;   case 3: return g_preB;
        case 4: return g_feat1;  case 5: return g_feat2;
        case 6: return g_saconv; case 7: return g_scconv;
        case 8: return g_safeat; default: return g_scfeat;
    }
}

__global__ void k_zeroall() {
    int idx = blockIdx.x * 256 + threadIdx.x;
    if (idx < BB*IC*IC) g_came[idx] = 0.f;
    if (idx < 4*IC) { g_sS[idx] = 0.f; g_sSS[idx] = 0.f; }
}

// ---------- conv1x1 from x (256 -> 128 combined outs), write at l+1 ----------
__global__ __launch_bounds__(256) void k_convx(const float* __restrict__ x,
                                               const float* __restrict__ W5a,
                                               const float* __restrict__ W5c) {
    int b = blockIdx.z, o0 = blockIdx.y * 64, l0 = blockIdx.x * 64;
    __shared__ float Ws[16][68], Xs[16][68];
    int tid = threadIdx.x, ty = tid / 16, tx = tid % 16;
    u64 acc[4][2] = {};
    const float* xb = x + (size_t)b * CIN * LIN;
    for (int kc = 0; kc < CIN; kc += 16) {
#pragma unroll
        for (int t = 0; t < 4; t++) {
            int i = tid + t * 256, k = i / 64, o = i % 64;
            int oo = o0 + o;
            const float* Wp = (oo < IC) ? (W5a + oo * CIN) : (W5c + (oo - IC) * CIN);
            Ws[k][o] = Wp[kc + k];
        }
#pragma unroll
        for (int t = 0; t < 4; t++) {
            int i = tid + t * 256, k = i / 64, l = i % 64;
            int gl = l0 + l;
            Xs[k][l] = (gl < LIN) ? xb[(size_t)(kc + k) * LIN + gl] : 0.f;
        }
        __syncthreads();
#pragma unroll
        for (int k = 0; k < 16; k++) {
            float4 a = *(float4*)&Ws[k][ty * 4];
            u64 b01 = *(u64*)&Xs[k][tx * 4];
            u64 b23 = *(u64*)&Xs[k][tx * 4 + 2];
            u64 a0 = pk2(a.x, a.x), a1 = pk2(a.y, a.y), a2 = pk2(a.z, a.z), a3 = pk2(a.w, a.w);
            fma2(acc[0][0], a0, b01); fma2(acc[0][1], a0, b23);
            fma2(acc[1][0], a1, b01); fma2(acc[1][1], a1, b23);
            fma2(acc[2][0], a2, b01); fma2(acc[2][1], a2, b23);
            fma2(acc[3][0], a3, b01); fma2(acc[3][1], a3, b23);
        }
        __syncthreads();
    }
#pragma unroll
    for (int i = 0; i < 4; i++) {
        int o = o0 + ty * 4 + i;
        float* dst = (o < IC) ? (g_pre1 + ((size_t)b * IC + o) * LPAD)
                              : (g_pre2 + ((size_t)b * IC + (o - IC)) * LPAD);
        float2 p0 = up2(acc[i][0]), p1 = up2(acc[i][1]);
        float vv[4] = {p0.x, p0.y, p1.x, p1.y};
#pragma unroll
        for (int j = 0; j < 4; j++) {
            int l = l0 + tx * 4 + j;
            if (l < LIN) dst[l + 1] = vv[j];
        }
    }
}

// ---------- BN stats: partial sums per (ch, b), atomic accumulate ----------
__global__ void k_stats(int sel, int slot, int border) {
    int ch = blockIdx.x, b = blockIdx.y;
    const float* pre = selbuf(sel) + ((size_t)b * IC + ch) * LPAD;
    int lo = border ? 1 : 0, cnt = border ? (LPAD - 2) : LPAD;
    float s = 0.f, ss = 0.f;
    for (int l = threadIdx.x; l < cnt; l += 256) {
        float v = pre[lo + l];
        s += v; ss += v * v;
    }
#pragma unroll
    for (int off = 16; off > 0; off >>= 1) {
        s  += __shfl_xor_sync(0xffffffffu, s, off);
        ss += __shfl_xor_sync(0xffffffffu, ss, off);
    }
    __shared__ float r1[8], r2[8];
    int lane = threadIdx.x & 31, wid = threadIdx.x >> 5;
    if (lane == 0) { r1[wid] = s; r2[wid] = ss; }
    __syncthreads();
    if (threadIdx.x == 0) {
        float S = 0.f, SS = 0.f;
        for (int w = 0; w < 8; w++) { S += r1[w]; SS += r2[w]; }
        atomicAdd(&g_sS[slot * IC + ch], S);
        atomicAdd(&g_sSS[slot * IC + ch], SS);
    }
}

// ---------- BN + ReLU (float4), stats finalized inline ----------
__global__ void k_bnrelu(int psel, int osel, const float* __restrict__ g,
                         const float* __restrict__ bia, int slot, int border) {
    const float4* pre = (const float4*)selbuf(psel);
    float4* out = (float4*)selbuf(osel);
    int idx = blockIdx.x * 256 + threadIdx.x;     // float4 index
    int l4 = idx & 511;
    int c = (idx >> 9) & (IC - 1);
    float4 v = pre[idx];
    if (border) { if (l4 == 0) v.x = 0.f; if (l4 == 511) v.w = 0.f; }
    float N = (float)(BB * LPAD);
    float mu = g_sS[slot * IC + c] / N;
    float rs = rsqrtf(g_sSS[slot * IC + c] / N - mu * mu + BNEPS);
    float sc = rs * g[c], sb = bia[c] - mu * sc;
    float4 r;
    r.x = fmaxf(v.x * sc + sb, 0.f); r.y = fmaxf(v.y * sc + sb, 0.f);
    r.z = fmaxf(v.z * sc + sb, 0.f); r.w = fmaxf(v.w * sc + sb, 0.f);
    out[idx] = r;
}

// ---------- q/k/v from feat1 (80 outputs) ----------
__global__ __launch_bounds__(256) void k_qkv(const float* __restrict__ Wq, const float* __restrict__ bq,
                                             const float* __restrict__ Wk, const float* __restrict__ bk,
                                             const float* __restrict__ Wv, const float* __restrict__ bvw) {
    int b = blockIdx.y, l0 = blockIdx.x * 64;
    __shared__ float Wsm[80][65], Fs[64][65];
    int tid = threadIdx.x;
    for (int i = tid; i < 80 * 64; i += 256) {
        int o = i / 64, k = i % 64;
        float v;
        if (o < 8)       v = Wq[o * IC + k];
        else if (o < 16) v = Wk[(o - 8) * IC + k];
        else             v = Wv[(o - 16) * IC + k];
        Wsm[o][k] = v;
    }
    const float* f1 = g_feat1 + (size_t)b * IC * LPAD;
    for (int i = tid; i < 64 * 64; i += 256) {
        int k = i / 64, l = i % 64;
        Fs[k][l] = f1[(size_t)k * LPAD + l0 + l];
    }
    __syncthreads();
    int l = tid % 64, ob = tid / 64;
    float acc[20] = {};
#pragma unroll 8
    for (int k = 0; k < 64; k++) {
        float fl = Fs[k][l];
#pragma unroll
        for (int t = 0; t < 20; t++) acc[t] += Wsm[ob + t * 4][k] * fl;
    }
#pragma unroll
    for (int t = 0; t < 20; t++) {
        int o = ob + t * 4;
        float bias = (o < 8) ? bq[o] : ((o < 16) ? bk[o - 8] : bvw[o - 16]);
        float val = acc[t] + bias;
        if (o < 16) g_qk[((size_t)b * LPAD + l0 + l) * 16 + o] = val;
        else        g_v[((size_t)b * IC + (o - 16)) * LPAD + l0 + l] = val;
    }
}

// ---------- per-row softmax stats ----------
__global__ void k_rowstats() {
    int b = blockIdx.y;
    int l = blockIdx.x * 8 + threadIdx.y;
    int lane = threadIdx.x;
    const float4* qp = (const float4*)(g_qk + ((size_t)b * LPAD + l) * 16);
    float4 q0 = qp[0], q1 = qp[1];
    float mx = -1e30f, sm = 0.f;
    for (int m = lane; m < LPAD; m += 32) {
        const float4* kp = (const float4*)(g_qk + ((size_t)b * LPAD + m) * 16 + 8);
        float4 k0 = kp[0], k1 = kp[1];
        float s = q0.x * k0.x + q0.y * k0.y + q0.z * k0.z + q0.w * k0.w
                + q1.x * k1.x + q1.y * k1.y + q1.z * k1.z + q1.w * k1.w;
        if (s <= mx) sm += __expf(s - mx);
        else { sm = sm * __expf(mx - s) + 1.f; mx = s; }
    }
#pragma unroll
    for (int off = 16; off > 0; off >>= 1) {
        float om = __shfl_xor_sync(0xffffffffu, mx, off);
        float os = __shfl_xor_sync(0xffffffffu, sm, off);
        float nm = fmaxf(mx, om);
        sm = sm * __expf(mx - nm) + os * __expf(om - nm);
        mx = nm;
    }
    if (lane == 0) { g_rowM[b * LPAD + l] = mx; g_rowI[b * LPAD + l] = 1.f / sm; }
}

// ---------- PAM: fused scores + softmax + V-accum (f32x2) ----------
__global__ __launch_bounds__(256) void k_pamout(const float* __restrict__ gamma) {
    int b = blockIdx.y, l0 = blockIdx.x * 64;
    __shared__ float qsm[64][9], ks[8][65], vs[64][65], psT[64][68];
    __shared__ float Ms[64], Is[64];
    int tid = threadIdx.x;
    for (int i = tid; i < 64 * 8; i += 256) {
        int l = i / 8, j = i % 8;
        qsm[l][j] = g_qk[((size_t)b * LPAD + l0 + l) * 16 + j];
    }
    if (tid < 64) { Ms[tid] = g_rowM[b * LPAD + l0 + tid]; Is[tid] = g_rowI[b * LPAD + l0 + tid]; }
    __syncthreads();
    int lq = tid & 63, mq = (tid >> 6) * 16;
    float qr[8];
#pragma unroll
    for (int j = 0; j < 8; j++) qr[j] = qsm[lq][j];
    float Mv = Ms[lq], Iv = Is[lq];
    int cy = (tid / 16) * 4, lx = (tid % 16) * 4;
    u64 acc[4][2] = {};
    for (int m0 = 0; m0 < LPAD; m0 += 64) {
        for (int i = tid; i < 512; i += 256) {
            int j = i / 64, m = i % 64;
            ks[j][m] = g_qk[((size_t)b * LPAD + m0 + m) * 16 + 8 + j];
        }
        for (int i = tid; i < 4096; i += 256) {
            int c = i / 64, m = i % 64;
            vs[c][m] = g_v[((size_t)b * IC + c) * LPAD + m0 + m];
        }
        __syncthreads();
#pragma unroll
        for (int t = 0; t < 16; t++) {
            int m = mq + t;
            float s = 0.f;
#pragma unroll
            for (int j = 0; j < 8; j++) s += qr[j] * ks[j][m];
            psT[m][lq] = __expf(s - Mv) * Iv;
        }
        __syncthreads();
#pragma unroll 4
        for (int m = 0; m < 64; m++) {
            u64 p01 = *(u64*)&psT[m][lx];
            u64 p23 = *(u64*)&psT[m][lx + 2];
#pragma unroll
            for (int i = 0; i < 4; i++) {
                float vv = vs[cy + i][m];
                u64 vp = pk2(vv, vv);
                fma2(acc[i][0], vp, p01);
                fma2(acc[i][1], vp, p23);
            }
        }
        __syncthreads();
    }
    float gm = gamma[0];
#pragma unroll
    for (int i = 0; i < 4; i++) {
        float2 p0 = up2(acc[i][0]), p1 = up2(acc[i][1]);
        float vv[4] = {p0.x, p0.y, p1.x, p1.y};
#pragma unroll
        for (int j = 0; j < 4; j++) {
            size_t idx = ((size_t)b * IC + cy + i) * LPAD + l0 + lx + j;
            g_safeat[idx] = gm * vv[j] + g_feat1[idx];
        }
    }
}

// ---------- CAM ----------
__global__ __launch_bounds__(256) void k_came() {
    int b = blockIdx.x, ls = blockIdx.y;
    __shared__ float Fs[64][33];
    int tid = threadIdx.x;
    int cy = (tid / 16) * 4, dx = (tid % 16) * 4;
    float acc[4][4] = {};
    const float* f2 = g_feat2 + (size_t)b * IC * LPAD;
    for (int lt = 0; lt < 4; lt++) {
        int l0 = ls * 128 + lt * 32;
        for (int i = tid; i < 64 * 32; i += 256) {
            int c = i / 32, j = i % 32;
            Fs[c][j] = f2[(size_t)c * LPAD + l0 + j];
        }
        __syncthreads();
#pragma unroll 8
        for (int j = 0; j < 32; j++) {
            float a[4], bv[4];
#pragma unroll
            for (int i = 0; i < 4; i++) a[i] = Fs[cy + i][j];
#pragma unroll
            for (int i = 0; i < 4; i++) bv[i] = Fs[dx + i][j];
#pragma unroll
            for (int i = 0; i < 4; i++)
#pragma unroll
                for (int jj = 0; jj < 4; jj++) acc[i][jj] += a[i] * bv[jj];
        }
        __syncthreads();
    }
#pragma unroll
    for (int i = 0; i < 4; i++)
#pragma unroll
        for (int jj = 0; jj < 4; jj++)
            atomicAdd(&g_came[b * 4096 + (cy + i) * 64 + dx + jj], acc[i][jj]);
}

__global__ void k_camsm() {
    int b = blockIdx.x >> 6, c = blockIdx.x & 63;
    int t = threadIdx.x;
    __shared__ float red[64];
    float e = g_came[b * 4096 + c * 64 + t];
    red[t] = e; __syncthreads();
    for (int st = 32; st > 0; st >>= 1) { if (t < st) red[t] = fmaxf(red[t], red[t + st]); __syncthreads(); }
    float rmax = red[0]; __syncthreads();
    float v = rmax - e;
    red[t] = v; __syncthreads();
    for (int st = 32; st > 0; st >>= 1) { if (t < st) red[t] = fmaxf(red[t], red[t + st]); __syncthreads(); }
    float vm = red[0]; __syncthreads();
    float p = __expf(v - vm);
    red[t] = p; __syncthreads();
    for (int st = 32; st > 0; st >>= 1) { if (t < st) red[t] += red[t + st]; __syncthreads(); }
    g_camattn[b * 4096 + c * 64 + t] = p / red[0];
}

__global__ __launch_bounds__(256) void k_camout(const float* __restrict__ gamma) {
    int b = blockIdx.y, l0 = blockIdx.x * 64;
    __shared__ float As[64][65], Fs[64][68];
    int tid = threadIdx.x;
    const float* f2 = g_feat2 + (size_t)b * IC * LPAD;
    for (int i = tid; i < 4096; i += 256) As[i / 64][i % 64] = g_camattn[b * 4096 + i];
    for (int i = tid; i < 4096; i += 256) {
        int d = i / 64, l = i % 64;
        Fs[d][l] = f2[(size_t)d * LPAD + l0 + l];
    }
    __syncthreads();
    int cy = (tid / 16) * 4, lx = (tid % 16) * 4;
    u64 acc[4][2] = {};
#pragma unroll 4
    for (int d = 0; d < 64; d++) {
        u64 b01 = *(u64*)&Fs[d][lx];
        u64 b23 = *(u64*)&Fs[d][lx + 2];
#pragma unroll
        for (int i = 0; i < 4; i++) {
            float a = As[cy + i][d];
            u64 ap = pk2(a, a);
            fma2(acc[i][0], ap, b01);
            fma2(acc[i][1], ap, b23);
        }
    }
    float gm = gamma[0];
#pragma unroll
    for (int i = 0; i < 4; i++) {
        float2 p0 = up2(acc[i][0]), p1 = up2(acc[i][1]);
        float vv[4] = {p0.x, p0.y, p1.x, p1.y};
#pragma unroll
        for (int j = 0; j < 4; j++) {
            size_t idx = ((size_t)b * IC + cy + i) * LPAD + l0 + lx + j;
            g_scfeat[idx] = gm * vv[j] + f2[(size_t)(cy + i) * LPAD + l0 + lx + j];
        }
    }
}

// ---------- conv3 pad1 (64 -> 64) ----------
__global__ __launch_bounds__(256) void k_conv3(int fsel, const float* __restrict__ W, int osel) {
    const float* f = selbuf(fsel);
    float* out = selbuf(osel);
    int b = blockIdx.y, l0 = blockIdx.x * 128;
    __shared__ float Fs[16][134], Ws2[16][194];
    int tid = threadIdx.x;
    int og = tid / 32, lg = tid % 32;
    float acc[8][4] = {};
    const float* fb = f + (size_t)b * IC * LPAD;
    for (int c0 = 0; c0 < 64; c0 += 16) {
        for (int i = tid; i < 2080; i += 256) {
            int cc = i / 130, j = i % 130;
            int gl = l0 + j - 1;
            Fs[cc][j] = (gl >= 0 && gl < LPAD) ? fb[(size_t)(c0 + cc) * LPAD + gl] : 0.f;
        }
        for (int i = tid; i < 3072; i += 256) {
            int o = i / 48, r = i % 48;
            Ws2[r / 3][o * 3 + (r % 3)] = W[o * 192 + c0 * 3 + r];
        }
        __syncthreads();
#pragma unroll
        for (int cc = 0; cc < 16; cc++) {
            float bv[7];
#pragma unroll
            for (int j = 0; j < 7; j++) bv[j] = Fs[cc][lg * 4 + j];
#pragma unroll
            for (int oi = 0; oi < 8; oi++) {
                int o = og * 8 + oi;
                float w0 = Ws2[cc][o * 3], w1 = Ws2[cc][o * 3 + 1], w2 = Ws2[cc][o * 3 + 2];
#pragma unroll
                for (int lj = 0; lj < 4; lj++)
                    acc[oi][lj] += w0 * bv[lj] + w1 * bv[lj + 1] + w2 * bv[lj + 2];
            }
        }
        __syncthreads();
    }
#pragma unroll
    for (int oi = 0; oi < 8; oi++)
#pragma unroll
        for (int lj = 0; lj < 4; lj++)
            out[((size_t)b * IC + og * 8 + oi) * LPAD + l0 + lg * 4 + lj] = acc[oi][lj];
}

// ---------- final 1x1 conv 64 -> 128 with bias (f32x2) ----------
__global__ __launch_bounds__(256) void k_out1x1(int ssel, const float* __restrict__ W,
                                                const float* __restrict__ bias,
                                                float* __restrict__ dst) {
    const float* src = selbuf(ssel);
    int b = blockIdx.z, o0 = blockIdx.y * 64, l0 = blockIdx.x * 64;
    __shared__ float Ws[16][68], Xs[16][68];
    int tid = threadIdx.x, ty = tid / 16, tx = tid % 16;
    u64 acc[4][2] = {};
    const float* sb = src + (size_t)b * IC * LPAD;
    for (int kc = 0; kc < 64; kc += 16) {
#pragma unroll
        for (int t = 0; t < 4; t++) {
            int i = tid + t * 256, k = i / 64, o = i % 64;
            Ws[k][o] = W[(o0 + o) * 64 + kc + k];
        }
#pragma unroll
        for (int t = 0; t < 4; t++) {
            int i = tid + t * 256, k = i / 64, l = i % 64;
            Xs[k][l] = sb[(size_t)(kc + k) * LPAD + l0 + l];
        }
        __syncthreads();
#pragma unroll
        for (int k = 0; k < 16; k++) {
            float4 a = *(float4*)&Ws[k][ty * 4];
            u64 b01 = *(u64*)&Xs[k][tx * 4];
            u64 b23 = *(u64*)&Xs[k][tx * 4 + 2];
            u64 a0 = pk2(a.x, a.x), a1 = pk2(a.y, a.y), a2 = pk2(a.z, a.z), a3 = pk2(a.w, a.w);
            fma2(acc[0][0], a0, b01); fma2(acc[0][1], a0, b23);
            fma2(acc[1][0], a1, b01); fma2(acc[1][1], a1, b23);
            fma2(acc[2][0], a2, b01); fma2(acc[2][1], a2, b23);
            fma2(acc[3][0], a3, b01); fma2(acc[3][1], a3, b23);
        }
        __syncthreads();
    }
#pragma unroll
    for (int i = 0; i < 4; i++) {
        int o = o0 + ty * 4 + i;
        float bs = bias[o];
        float2 p0 = up2(acc[i][0]), p1 = up2(acc[i][1]);
        float vv[4] = {p0.x, p0.y, p1.x, p1.y};
#pragma unroll
        for (int j = 0; j < 4; j++)
            dst[((size_t)b * OCH + o) * LPAD + l0 + tx * 4 + j] = vv[j] + bs;
    }
}

// ---------- column mean of (saconv + scconv) ----------
__global__ void k_colmean() {
    int b = blockIdx.x / IC, c = blockIdx.x % IC;
    const float4* p1 = (const float4*)(g_saconv + ((size_t)b * IC + c) * LPAD);
    const float4* p2 = (const float4*)(g_scconv + ((size_t)b * IC + c) * LPAD);
    float s = 0.f;
    for (int l = threadIdx.x; l < LPAD / 4; l += 128) {
        float4 a = p1[l], bq = p2[l];
        s += a.x + a.y + a.z + a.w + bq.x + bq.y + bq.z + bq.w;
    }
#pragma unroll
    for (int off = 16; off > 0; off >>= 1) s += __shfl_xor_sync(0xffffffffu, s, off);
    __shared__ float red[4];
    int lane = threadIdx.x & 31, wid = threadIdx.x >> 5;
    if (lane == 0) red[wid] = s;
    __syncthreads();
    if (threadIdx.x == 0)
        g_msum[b * IC + c] = (red[0] + red[1] + red[2] + red[3]) / (float)LPAD;
}

__global__ void k_sasc(const float* __restrict__ W8, const float* __restrict__ b8,
                       float* __restrict__ dout) {
    int b = blockIdx.x, o = threadIdx.x;
    float s = b8[o];
    for (int c = 0; c < IC; c++) s += W8[o * IC + c] * g_msum[b * IC + c];
    dout[b * OCH + o] = s;
}

extern "C" void kernel_launch(void* const* d_in, const int* in_sizes, int n_in,
                              void* d_out, int out_size) {
    const float* x   = (const float*)d_in[0];
    const float* W5a = (const float*)d_in[1];
    const float* g5a = (const float*)d_in[2];
    const float* b5a = (const float*)d_in[3];
    const float* W5c = (const float*)d_in[4];
    const float* g5c = (const float*)d_in[5];
    const float* b5c = (const float*)d_in[6];
    const float* Wq  = (const float*)d_in[7];
    const float* bq  = (const float*)d_in[8];
    const float* Wk  = (const float*)d_in[9];
    const float* bk  = (const float*)d_in[10];
    const float* Wv  = (const float*)d_in[11];
    const float* bv  = (const float*)d_in[12];
    const float* gpam = (const float*)d_in[13];
    const float* gcam = (const float*)d_in[14];
    const float* W51 = (const float*)d_in[15];
    const float* g51 = (const float*)d_in[16];
    const float* b51 = (const float*)d_in[17];
    const float* W52 = (const float*)d_in[18];
    const float* g52 = (const float*)d_in[19];
    const float* b52 = (const float*)d_in[20];
    const float* W6  = (const float*)d_in[21];
    const float* b6  = (const float*)d_in[22];
    const float* W7  = (const float*)d_in[23];
    const float* b7  = (const float*)d_in[24];
    const float* W8  = (const float*)d_in[25];
    const float* b8  = (const float*)d_in[26];
    float* out = (float*)d_out;
    const size_t OUTSZ = (size_t)BB * OCH * LPAD;

    k_zeroall<<<131, 256>>>();
    k_convx<<<dim3(32, 2, BB), 256>>>(x, W5a, W5c);
    k_stats<<<dim3(IC, BB), 256>>>(0, 0, 1);
    k_stats<<<dim3(IC, BB), 256>>>(1, 1, 1);
    k_bnrelu<<<1024, 256>>>(0, 4, g5a, b5a, 0, 1);
    k_bnrelu<<<1024, 256>>>(1, 5, g5c, b5c, 1, 1);

    // PAM branch
    k_qkv<<<dim3(32, BB), 256>>>(Wq, bq, Wk, bk, Wv, bv);
    k_rowstats<<<dim3(256, BB), dim3(32, 8)>>>();
    k_pamout<<<dim3(32, BB), 256>>>(gpam);
    k_conv3<<<dim3(16, BB), 256>>>(8, W51, 2);
    k_stats<<<dim3(IC, BB), 256>>>(2, 2, 0);
    k_bnrelu<<<1024, 256>>>(2, 6, g51, b51, 2, 0);
    k_out1x1<<<dim3(32, 2, BB), 256>>>(6, W6, b6, out + BB * OCH);

    // CAM branch
    k_came<<<dim3(BB, 16), 256>>>();
    k_camsm<<<BB * IC, 64>>>();
    k_camout<<<dim3(32, BB), 256>>>(gcam);
    k_conv3<<<dim3(16, BB), 256>>>(9, W52, 3);
    k_stats<<<dim3(IC, BB), 256>>>(3, 3, 0);
    k_bnrelu<<<1024, 256>>>(3, 7, g52, b52, 3, 0);
    k_out1x1<<<dim3(32, 2, BB), 256>>>(7, W7, b7, out + BB * OCH + OUTSZ);

    // fused mean path
    k_colmean<<<BB * IC, 128>>>();
    k_sasc<<<BB, OCH>>>(W8, b8, out);
}

// round 8
// speedup vs baseline: 1.1159x; 1.0369x over previous
#include <cuda_runtime.h>
#include <math.h>

#define BB   8
#define CIN  256
#define LIN  2046
#define LPAD 2048
#define IC   64
#define OCH  128
#define BNEPS 1e-5f
#define MT   32

typedef unsigned long long u64;
__device__ __forceinline__ u64 pk2(float x, float y) { u64 r; asm("mov.b64 %0,{%1,%2};" : "=l"(r) : "f"(x), "f"(y)); return r; }
__device__ __forceinline__ float2 up2(u64 v) { float2 r; asm("mov.b64 {%0,%1},%2;" : "=f"(r.x), "=f"(r.y) : "l"(v)); return r; }
__device__ __forceinline__ void fma2(u64& d, u64 a, u64 b) { asm("fma.rn.f32x2 %0,%1,%2,%0;" : "+l"(d) : "l"(a), "l"(b)); }

// ---------------- scratch ----------------
__device__ float g_pre1[BB*IC*LPAD];
__device__ float g_pre2[BB*IC*LPAD];
__device__ float g_preA[BB*IC*LPAD];
__device__ float g_preB[BB*IC*LPAD];
__device__ float g_feat1[BB*IC*LPAD];
__device__ float g_feat2[BB*IC*LPAD];
__device__ float g_saconv[BB*IC*LPAD];
__device__ float g_scconv[BB*IC*LPAD];
__device__ float g_safeat[BB*IC*LPAD];
__device__ float g_scfeat[BB*IC*LPAD];
__device__ float g_qk[BB*LPAD*16];
__device__ float g_v[BB*IC*LPAD];
__device__ float g_rowM[BB*LPAD];
__device__ float g_rowI[BB*LPAD];
__device__ float g_came[BB*IC*IC];
__device__ float g_msum[BB*IC];
__device__ float g_sS[4*IC];
__device__ float g_sSS[4*IC];

__device__ __forceinline__ float* selbuf(int s) {
    switch (s) {
        case 0: return g_pre1;   case 1: return g_pre2;
        case 2: return g_preA;   case 3: return g_preB;
        case 4: return g_feat1;  case 5: return g_feat2;
        case 6: return g_saconv; case 7: return g_scconv;
        case 8: return g_safeat; default: return g_scfeat;
    }
}

__global__ void k_zeroall() {
    int idx = blockIdx.x * 256 + threadIdx.x;
    if (idx < BB*IC*IC) g_came[idx] = 0.f;
    if (idx < 4*IC) { g_sS[idx] = 0.f; g_sSS[idx] = 0.f; }
}

// ---------- conv1x1 from x (256 -> 128 outs), write at l+1, fused BN stats ----------
__global__ __launch_bounds__(256) void k_convx(const float* __restrict__ x,
                                               const float* __restrict__ W5a,
                                               const float* __restrict__ W5c) {
    int b = blockIdx.z, o0 = blockIdx.y * 64, l0 = blockIdx.x * 64;
    __shared__ float Ws[16][68], Xs[16][68];
    int tid = threadIdx.x, ty = tid / 16, tx = tid % 16;
    u64 acc[4][2] = {};
    const float* xb = x + (size_t)b * CIN * LIN;
    for (int kc = 0; kc < CIN; kc += 16) {
#pragma unroll
        for (int t = 0; t < 4; t++) {
            int i = tid + t * 256, k = i / 64, o = i % 64;
            int oo = o0 + o;
            const float* Wp = (oo < IC) ? (W5a + oo * CIN) : (W5c + (oo - IC) * CIN);
            Ws[k][o] = Wp[kc + k];
        }
#pragma unroll
        for (int t = 0; t < 4; t++) {
            int i = tid + t * 256, k = i / 64, l = i % 64;
            int gl = l0 + l;
            Xs[k][l] = (gl < LIN) ? xb[(size_t)(kc + k) * LIN + gl] : 0.f;
        }
        __syncthreads();
#pragma unroll
        for (int k = 0; k < 16; k++) {
            float4 a = *(float4*)&Ws[k][ty * 4];
            u64 b01 = *(u64*)&Xs[k][tx * 4];
            u64 b23 = *(u64*)&Xs[k][tx * 4 + 2];
            u64 a0 = pk2(a.x, a.x), a1 = pk2(a.y, a.y), a2 = pk2(a.z, a.z), a3 = pk2(a.w, a.w);
            fma2(acc[0][0], a0, b01); fma2(acc[0][1], a0, b23);
            fma2(acc[1][0], a1, b01); fma2(acc[1][1], a1, b23);
            fma2(acc[2][0], a2, b01); fma2(acc[2][1], a2, b23);
            fma2(acc[3][0], a3, b01); fma2(acc[3][1], a3, b23);
        }
        __syncthreads();
    }
    int slot = blockIdx.y;       // 0 -> pre1/slot0, 1 -> pre2/slot1
#pragma unroll
    for (int i = 0; i < 4; i++) {
        int o = o0 + ty * 4 + i;
        float* dst = (o < IC) ? (g_pre1 + ((size_t)b * IC + o) * LPAD)
                              : (g_pre2 + ((size_t)b * IC + (o - IC)) * LPAD);
        float2 p0 = up2(acc[i][0]), p1 = up2(acc[i][1]);
        float vv[4] = {p0.x, p0.y, p1.x, p1.y};
        float s = 0.f, ss = 0.f;
#pragma unroll
        for (int j = 0; j < 4; j++) {
            int l = l0 + tx * 4 + j;
            if (l < LIN) { dst[l + 1] = vv[j]; s += vv[j]; ss += vv[j] * vv[j]; }
        }
#pragma unroll
        for (int off = 8; off > 0; off >>= 1) {
            s  += __shfl_xor_sync(0xffffffffu, s, off);
            ss += __shfl_xor_sync(0xffffffffu, ss, off);
        }
        if (tx == 0) {
            int ch = (o < IC) ? o : (o - IC);
            atomicAdd(&g_sS[slot * IC + ch], s);
            atomicAdd(&g_sSS[slot * IC + ch], ss);
        }
    }
}

// ---------- BN + ReLU (float4), dual-slot via grid.z ----------
__global__ void k_bnrelu01(const float* __restrict__ g0, const float* __restrict__ bia0,
                           const float* __restrict__ g1, const float* __restrict__ bia1) {
    int z = blockIdx.z;
    const float4* pre = (const float4*)selbuf(z);
    float4* out = (float4*)selbuf(4 + z);
    const float* g = z ? g1 : g0;
    const float* bia = z ? bia1 : bia0;
    int idx = blockIdx.x * 256 + threadIdx.x;
    int l4 = idx & 511;
    int c = (idx >> 9) & (IC - 1);
    float4 v = pre[idx];
    if (l4 == 0) v.x = 0.f;
    if (l4 == 511) v.w = 0.f;
    float N = (float)(BB * LPAD);
    float mu = g_sS[z * IC + c] / N;
    float rs = rsqrtf(g_sSS[z * IC + c] / N - mu * mu + BNEPS);
    float sc = rs * g[c], sb = bia[c] - mu * sc;
    float4 r;
    r.x = fmaxf(v.x * sc + sb, 0.f); r.y = fmaxf(v.y * sc + sb, 0.f);
    r.z = fmaxf(v.z * sc + sb, 0.f); r.w = fmaxf(v.w * sc + sb, 0.f);
    out[idx] = r;
}

__global__ void k_bnrelu(int psel, int osel, const float* __restrict__ g,
                         const float* __restrict__ bia, int slot) {
    const float4* pre = (const float4*)selbuf(psel);
    float4* out = (float4*)selbuf(osel);
    int idx = blockIdx.x * 256 + threadIdx.x;
    int c = (idx >> 9) & (IC - 1);
    float4 v = pre[idx];
    float N = (float)(BB * LPAD);
    float mu = g_sS[slot * IC + c] / N;
    float rs = rsqrtf(g_sSS[slot * IC + c] / N - mu * mu + BNEPS);
    float sc = rs * g[c], sb = bia[c] - mu * sc;
    float4 r;
    r.x = fmaxf(v.x * sc + sb, 0.f); r.y = fmaxf(v.y * sc + sb, 0.f);
    r.z = fmaxf(v.z * sc + sb, 0.f); r.w = fmaxf(v.w * sc + sb, 0.f);
    out[idx] = r;
}

// ---------- q/k/v from feat1 (80 outputs) ----------
__global__ __launch_bounds__(256) void k_qkv(const float* __restrict__ Wq, const float* __restrict__ bq,
                                             const float* __restrict__ Wk, const float* __restrict__ bk,
                                             const float* __restrict__ Wv, const float* __restrict__ bvw) {
    int b = blockIdx.y, l0 = blockIdx.x * 64;
    __shared__ float Wsm[80][65], Fs[64][65];
    int tid = threadIdx.x;
    for (int i = tid; i < 80 * 64; i += 256) {
        int o = i / 64, k = i % 64;
        float v;
        if (o < 8)       v = Wq[o * IC + k];
        else if (o < 16) v = Wk[(o - 8) * IC + k];
        else             v = Wv[(o - 16) * IC + k];
        Wsm[o][k] = v;
    }
    const float* f1 = g_feat1 + (size_t)b * IC * LPAD;
    for (int i = tid; i < 64 * 64; i += 256) {
        int k = i / 64, l = i % 64;
        Fs[k][l] = f1[(size_t)k * LPAD + l0 + l];
    }
    __syncthreads();
    int l = tid % 64, ob = tid / 64;
    float acc[20] = {};
#pragma unroll 8
    for (int k = 0; k < 64; k++) {
        float fl = Fs[k][l];
#pragma unroll
        for (int t = 0; t < 20; t++) acc[t] += Wsm[ob + t * 4][k] * fl;
    }
#pragma unroll
    for (int t = 0; t < 20; t++) {
        int o = ob + t * 4;
        float bias = (o < 8) ? bq[o] : ((o < 16) ? bk[o - 8] : bvw[o - 16]);
        float val = acc[t] + bias;
        if (o < 16) g_qk[((size_t)b * LPAD + l0 + l) * 16 + o] = val;
        else        g_v[((size_t)b * IC + (o - 16)) * LPAD + l0 + l] = val;
    }
}

// ---------- per-row softmax stats ----------
__global__ void k_rowstats() {
    int b = blockIdx.y;
    int l = blockIdx.x * 8 + threadIdx.y;
    int lane = threadIdx.x;
    const float4* qp = (const float4*)(g_qk + ((size_t)b * LPAD + l) * 16);
    float4 q0 = qp[0], q1 = qp[1];
    float mx = -1e30f, sm = 0.f;
    for (int m = lane; m < LPAD; m += 32) {
        const float4* kp = (const float4*)(g_qk + ((size_t)b * LPAD + m) * 16 + 8);
        float4 k0 = kp[0], k1 = kp[1];
        float s = q0.x * k0.x + q0.y * k0.y + q0.z * k0.z + q0.w * k0.w
                + q1.x * k1.x + q1.y * k1.y + q1.z * k1.z + q1.w * k1.w;
        if (s <= mx) sm += __expf(s - mx);
        else { sm = sm * __expf(mx - s) + 1.f; mx = s; }
    }
#pragma unroll
    for (int off = 16; off > 0; off >>= 1) {
        float om = __shfl_xor_sync(0xffffffffu, mx, off);
        float os = __shfl_xor_sync(0xffffffffu, sm, off);
        float nm = fmaxf(mx, om);
        sm = sm * __expf(mx - nm) + os * __expf(om - nm);
        mx = nm;
    }
    if (lane == 0) { g_rowM[b * LPAD + l] = mx; g_rowI[b * LPAD + l] = 1.f / sm; }
}

// ---------- PAM fused: scores + softmax + V-accum + epilogue ----------
__global__ __launch_bounds__(256) void k_pamout(const float* __restrict__ gamma) {
    int b = blockIdx.y, l0 = blockIdx.x * 128;   // grid (16, 8)
    __shared__ u64  ksp[4][36];        // packed k pairs [pair][m]
    __shared__ float psT[MT][132];     // probabilities [m][l]
    __shared__ float vsmT[MT][68];     // v transposed  [m][c]
    int tid = threadIdx.x;
    int lq = tid & 127, mh = tid >> 7;
    const float4* qp4 = (const float4*)(g_qk + ((size_t)b * LPAD + l0 + lq) * 16);
    float4 q0 = qp4[0], q1 = qp4[1];
    u64 qp[4] = { pk2(q0.x, q0.y), pk2(q0.z, q0.w), pk2(q1.x, q1.y), pk2(q1.z, q1.w) };
    float Mv = g_rowM[b * LPAD + l0 + lq], Iv = g_rowI[b * LPAD + l0 + lq];
    int cy = (tid >> 5) * 8, lx = (tid & 31) * 4;
    u64 acc[8][2] = {};
    const float* vb = g_v + (size_t)b * IC * LPAD;
    for (int m0 = 0; m0 < LPAD; m0 += MT) {
        if (tid < 128) {
            int p = tid >> 5, m = tid & 31;
            float2 kv = *(const float2*)(g_qk + ((size_t)b * LPAD + m0 + m) * 16 + 8 + 2 * p);
            ksp[p][m] = pk2(kv.x, kv.y);
        }
#pragma unroll
        for (int t = 0; t < 2; t++) {
            int i = tid + t * 256;
            int c = i >> 3, m4 = (i & 7) * 4;
            float4 v = *(const float4*)(vb + (size_t)c * LPAD + m0 + m4);
            vsmT[m4 + 0][c] = v.x; vsmT[m4 + 1][c] = v.y;
            vsmT[m4 + 2][c] = v.z; vsmT[m4 + 3][c] = v.w;
        }
        __syncthreads();
#pragma unroll
        for (int t = 0; t < 16; t++) {
            int m = mh * 16 + t;
            u64 s2 = 0ull;
            fma2(s2, qp[0], ksp[0][m]); fma2(s2, qp[1], ksp[1][m]);
            fma2(s2, qp[2], ksp[2][m]); fma2(s2, qp[3], ksp[3][m]);
            float2 sv = up2(s2);
            psT[m][lq] = __expf(sv.x + sv.y - Mv) * Iv;
        }
        __syncthreads();
#pragma unroll 4
        for (int m = 0; m < MT; m++) {
            u64 p01 = *(u64*)&psT[m][lx];
            u64 p23 = *(u64*)&psT[m][lx + 2];
            float4 v0 = *(float4*)&vsmT[m][cy];
            float4 v1 = *(float4*)&vsmT[m][cy + 4];
            u64 d0 = pk2(v0.x, v0.x), d1 = pk2(v0.y, v0.y), d2 = pk2(v0.z, v0.z), d3 = pk2(v0.w, v0.w);
            u64 d4 = pk2(v1.x, v1.x), d5 = pk2(v1.y, v1.y), d6 = pk2(v1.z, v1.z), d7 = pk2(v1.w, v1.w);
            fma2(acc[0][0], d0, p01); fma2(acc[0][1], d0, p23);
            fma2(acc[1][0], d1, p01); fma2(acc[1][1], d1, p23);
            fma2(acc[2][0], d2, p01); fma2(acc[2][1], d2, p23);
            fma2(acc[3][0], d3, p01); fma2(acc[3][1], d3, p23);
            fma2(acc[4][0], d4, p01); fma2(acc[4][1], d4, p23);
            fma2(acc[5][0], d5, p01); fma2(acc[5][1], d5, p23);
            fma2(acc[6][0], d6, p01); fma2(acc[6][1], d6, p23);
            fma2(acc[7][0], d7, p01); fma2(acc[7][1], d7, p23);
        }
        __syncthreads();
    }
    float gm = gamma[0];
#pragma unroll
    for (int i = 0; i < 8; i++) {
        size_t row = ((size_t)b * IC + cy + i) * LPAD + l0 + lx;
        float2 a0 = up2(acc[i][0]), a1 = up2(acc[i][1]);
        float4 f = *(const float4*)(g_feat1 + row);
        float4 r;
        r.x = gm * a0.x + f.x; r.y = gm * a0.y + f.y;
        r.z = gm * a1.x + f.z; r.w = gm * a1.y + f.w;
        *(float4*)(g_safeat + row) = r;
    }
}

// ---------- CAM energy ----------
__global__ __launch_bounds__(256) void k_came() {
    int b = blockIdx.x, ls = blockIdx.y;
    __shared__ float Fs[64][33];
    int tid = threadIdx.x;
    int cy = (tid / 16) * 4, dx = (tid % 16) * 4;
    float acc[4][4] = {};
    const float* f2 = g_feat2 + (size_t)b * IC * LPAD;
    for (int lt = 0; lt < 4; lt++) {
        int l0 = ls * 128 + lt * 32;
        for (int i = tid; i < 512; i += 256) {
            int c = i / 8, w = (i % 8) * 4;
            float4 v = *(const float4*)(f2 + (size_t)c * LPAD + l0 + w);
            Fs[c][w] = v.x; Fs[c][w + 1] = v.y; Fs[c][w + 2] = v.z; Fs[c][w + 3] = v.w;
        }
        __syncthreads();
#pragma unroll 8
        for (int j = 0; j < 32; j++) {
            float a[4], bv[4];
#pragma unroll
            for (int i = 0; i < 4; i++) a[i] = Fs[cy + i][j];
#pragma unroll
            for (int i = 0; i < 4; i++) bv[i] = Fs[dx + i][j];
#pragma unroll
            for (int i = 0; i < 4; i++)
#pragma unroll
                for (int jj = 0; jj < 4; jj++) acc[i][jj] += a[i] * bv[jj];
        }
        __syncthreads();
    }
#pragma unroll
    for (int i = 0; i < 4; i++)
#pragma unroll
        for (int jj = 0; jj < 4; jj++)
            atomicAdd(&g_came[b * 4096 + (cy + i) * 64 + dx + jj], acc[i][jj]);
}

// ---------- CAM: softmax (folded) + out GEMM + epilogue ----------
__global__ __launch_bounds__(256) void k_camout(const float* __restrict__ gamma) {
    int b = blockIdx.y, l0 = blockIdx.x * 64;
    __shared__ float As[64][65], Fs[64][68];
    int tid = threadIdx.x;
    const float* f2 = g_feat2 + (size_t)b * IC * LPAD;
    for (int i = tid; i < 4096; i += 256) As[i / 64][i % 64] = g_came[b * 4096 + i];
    for (int i = tid; i < 1024; i += 256) {
        int d = i / 16, w = (i % 16) * 4;
        float4 v = *(const float4*)(f2 + (size_t)d * LPAD + l0 + w);
        Fs[d][w] = v.x; Fs[d][w + 1] = v.y; Fs[d][w + 2] = v.z; Fs[d][w + 3] = v.w;
    }
    __syncthreads();
    {
        int r = tid / 4, q = tid % 4;
        float e[16];
        float mn = 1e30f;
#pragma unroll
        for (int k = 0; k < 16; k++) { e[k] = As[r][q * 16 + k]; mn = fminf(mn, e[k]); }
        mn = fminf(mn, __shfl_xor_sync(0xffffffffu, mn, 1));
        mn = fminf(mn, __shfl_xor_sync(0xffffffffu, mn, 2));
        float s = 0.f;
#pragma unroll
        for (int k = 0; k < 16; k++) { e[k] = __expf(mn - e[k]); s += e[k]; }
        s += __shfl_xor_sync(0xffffffffu, s, 1);
        s += __shfl_xor_sync(0xffffffffu, s, 2);
        float inv = 1.f / s;
#pragma unroll
        for (int k = 0; k < 16; k++) As[r][q * 16 + k] = e[k] * inv;
    }
    __syncthreads();
    int cy = (tid / 16) * 4, lx = (tid % 16) * 4;
    u64 acc[4][2] = {};
#pragma unroll 4
    for (int d = 0; d < 64; d++) {
        u64 b01 = *(u64*)&Fs[d][lx];
        u64 b23 = *(u64*)&Fs[d][lx + 2];
#pragma unroll
        for (int i = 0; i < 4; i++) {
            float a = As[cy + i][d];
            u64 ap = pk2(a, a);
            fma2(acc[i][0], ap, b01);
            fma2(acc[i][1], ap, b23);
        }
    }
    float gm = gamma[0];
#pragma unroll
    for (int i = 0; i < 4; i++) {
        size_t row = ((size_t)b * IC + cy + i) * LPAD + l0 + lx;
        float2 a0 = up2(acc[i][0]), a1 = up2(acc[i][1]);
        float4 f = *(const float4*)(f2 + (size_t)(cy + i) * LPAD + l0 + lx);
        float4 r;
        r.x = gm * a0.x + f.x; r.y = gm * a0.y + f.y;
        r.z = gm * a1.x + f.z; r.w = gm * a1.y + f.w;
        *(float4*)(g_scfeat + row) = r;
    }
}

// ---------- conv3 pad1 (64 -> 64), f32x2, fused BN stats ----------
__global__ __launch_bounds__(256) void k_conv3(int fsel, const float* __restrict__ W, int osel, int slot) {
    const float* f = selbuf(fsel);
    float* out = selbuf(osel);
    int b = blockIdx.y, l0 = blockIdx.x * 128;
    __shared__ float Fs[16][134], Ws2[16][194];
    int tid = threadIdx.x;
    int og = tid / 32, lg = tid % 32;
    u64 acc[8][2] = {};
    const float* fb = f + (size_t)b * IC * LPAD;
    for (int c0 = 0; c0 < 64; c0 += 16) {
        for (int i = tid; i < 2080; i += 256) {
            int cc = i / 130, j = i % 130;
            int gl = l0 + j - 1;
            Fs[cc][j] = (gl >= 0 && gl < LPAD) ? fb[(size_t)(c0 + cc) * LPAD + gl] : 0.f;
        }
        for (int i = tid; i < 3072; i += 256) {
            int o = i / 48, r = i % 48;
            Ws2[r / 3][o * 3 + (r % 3)] = W[o * 192 + c0 * 3 + r];
        }
        __syncthreads();
#pragma unroll
        for (int cc = 0; cc < 16; cc++) {
            float bv[6];
#pragma unroll
            for (int j = 0; j < 6; j++) bv[j] = Fs[cc][lg * 4 + j];
            u64 A = pk2(bv[0], bv[1]), Bp = pk2(bv[1], bv[2]), C = pk2(bv[2], bv[3]);
            u64 D = pk2(bv[3], bv[4]), E = pk2(bv[4], bv[5]);
#pragma unroll
            for (int oi = 0; oi < 8; oi++) {
                int o = og * 8 + oi;
                float w0 = Ws2[cc][o * 3], w1 = Ws2[cc][o * 3 + 1], w2 = Ws2[cc][o * 3 + 2];
                u64 w0d = pk2(w0, w0), w1d = pk2(w1, w1), w2d = pk2(w2, w2);
                fma2(acc[oi][0], w0d, A); fma2(acc[oi][0], w1d, Bp); fma2(acc[oi][0], w2d, C);
                fma2(acc[oi][1], w0d, C); fma2(acc[oi][1], w1d, D);  fma2(acc[oi][1], w2d, E);
            }
        }
        __syncthreads();
    }
#pragma unroll
    for (int oi = 0; oi < 8; oi++) {
        float2 x0 = up2(acc[oi][0]), x1 = up2(acc[oi][1]);
        float4 r; r.x = x0.x; r.y = x0.y; r.z = x1.x; r.w = x1.y;
        *(float4*)(out + ((size_t)b * IC + og * 8 + oi) * LPAD + l0 + lg * 4) = r;
        float s = r.x + r.y + r.z + r.w;
        float ss = r.x * r.x + r.y * r.y + r.z * r.z + r.w * r.w;
#pragma unroll
        for (int off = 16; off > 0; off >>= 1) {
            s  += __shfl_xor_sync(0xffffffffu, s, off);
            ss += __shfl_xor_sync(0xffffffffu, ss, off);
        }
        if (lg == 0) {
            atomicAdd(&g_sS[slot * IC + og * 8 + oi], s);
            atomicAdd(&g_sSS[slot * IC + og * 8 + oi], ss);
        }
    }
}

// ---------- final 1x1 conv 64 -> 128 ----------
__global__ __launch_bounds__(256) void k_out1x1(int ssel, const float* __restrict__ W,
                                                const float* __restrict__ bias,
                                                float* __restrict__ dst) {
    const float* src = selbuf(ssel);
    int b = blockIdx.z, o0 = blockIdx.y * 64, l0 = blockIdx.x * 64;
    __shared__ float Ws[16][68], Xs[16][68];
    int tid = threadIdx.x, ty = tid / 16, tx = tid % 16;
    u64 acc[4][2] = {};
    const float* sb = src + (size_t)b * IC * LPAD;
    for (int kc = 0; kc < 64; kc += 16) {
#pragma unroll
        for (int t = 0; t < 4; t++) {
            int i = tid + t * 256, k = i / 64, o = i % 64;
            Ws[k][o] = W[(o0 + o) * 64 + kc + k];
        }
#pragma unroll
        for (int t = 0; t < 4; t++) {
            int i = tid + t * 256, k = i / 64, l = i % 64;
            Xs[k][l] = sb[(size_t)(kc + k) * LPAD + l0 + l];
        }
        __syncthreads();
#pragma unroll
        for (int k = 0; k < 16; k++) {
            float4 a = *(float4*)&Ws[k][ty * 4];
            u64 b01 = *(u64*)&Xs[k][tx * 4];
            u64 b23 = *(u64*)&Xs[k][tx * 4 + 2];
            u64 a0 = pk2(a.x, a.x), a1 = pk2(a.y, a.y), a2 = pk2(a.z, a.z), a3 = pk2(a.w, a.w);
            fma2(acc[0][0], a0, b01); fma2(acc[0][1], a0, b23);
            fma2(acc[1][0], a1, b01); fma2(acc[1][1], a1, b23);
            fma2(acc[2][0], a2, b01); fma2(acc[2][1], a2, b23);
            fma2(acc[3][0], a3, b01); fma2(acc[3][1], a3, b23);
        }
        __syncthreads();
    }
#pragma unroll
    for (int i = 0; i < 4; i++) {
        int o = o0 + ty * 4 + i;
        float bs = bias[o];
        float2 p0 = up2(acc[i][0]), p1 = up2(acc[i][1]);
        float4 r; r.x = p0.x + bs; r.y = p0.y + bs; r.z = p1.x + bs; r.w = p1.y + bs;
        *(float4*)(dst + ((size_t)b * OCH + o) * LPAD + l0 + tx * 4) = r;
    }
}

// ---------- column mean of (saconv + scconv) ----------
__global__ void k_colmean() {
    int b = blockIdx.x / IC, c = blockIdx.x % IC;
    const float4* p1 = (const float4*)(g_saconv + ((size_t)b * IC + c) * LPAD);
    const float4* p2 = (const float4*)(g_scconv + ((size_t)b * IC + c) * LPAD);
    float s = 0.f;
    for (int l = threadIdx.x; l < LPAD / 4; l += 128) {
        float4 a = p1[l], bq = p2[l];
        s += a.x + a.y + a.z + a.w + bq.x + bq.y + bq.z + bq.w;
    }
#pragma unroll
    for (int off = 16; off > 0; off >>= 1) s += __shfl_xor_sync(0xffffffffu, s, off);
    __shared__ float red[4];
    int lane = threadIdx.x & 31, wid = threadIdx.x >> 5;
    if (lane == 0) red[wid] = s;
    __syncthreads();
    if (threadIdx.x == 0)
        g_msum[b * IC + c] = (red[0] + red[1] + red[2] + red[3]) / (float)LPAD;
}

__global__ void k_sasc(const float* __restrict__ W8, const float* __restrict__ b8,
                       float* __restrict__ dout) {
    int b = blockIdx.x, o = threadIdx.x;
    float s = b8[o];
    for (int c = 0; c < IC; c++) s += W8[o * IC + c] * g_msum[b * IC + c];
    dout[b * OCH + o] = s;
}

extern "C" void kernel_launch(void* const* d_in, const int* in_sizes, int n_in,
                              void* d_out, int out_size) {
    const float* x   = (const float*)d_in[0];
    const float* W5a = (const float*)d_in[1];
    const float* g5a = (const float*)d_in[2];
    const float* b5a = (const float*)d_in[3];
    const float* W5c = (const float*)d_in[4];
    const float* g5c = (const float*)d_in[5];
    const float* b5c = (const float*)d_in[6];
    const float* Wq  = (const float*)d_in[7];
    const float* bq  = (const float*)d_in[8];
    const float* Wk  = (const float*)d_in[9];
    const float* bk  = (const float*)d_in[10];
    const float* Wv  = (const float*)d_in[11];
    const float* bv  = (const float*)d_in[12];
    const float* gpam = (const float*)d_in[13];
    const float* gcam = (const float*)d_in[14];
    const float* W51 = (const float*)d_in[15];
    const float* g51 = (const float*)d_in[16];
    const float* b51 = (const float*)d_in[17];
    const float* W52 = (const float*)d_in[18];
    const float* g52 = (const float*)d_in[19];
    const float* b52 = (const float*)d_in[20];
    const float* W6  = (const float*)d_in[21];
    const float* b6  = (const float*)d_in[22];
    const float* W7  = (const float*)d_in[23];
    const float* b7  = (const float*)d_in[24];
    const float* W8  = (const float*)d_in[25];
    const float* b8  = (const float*)d_in[26];
    float* out = (float*)d_out;
    const size_t OUTSZ = (size_t)BB * OCH * LPAD;

    k_zeroall<<<131, 256>>>();
    k_convx<<<dim3(32, 2, BB), 256>>>(x, W5a, W5c);          // + BN stats slots 0,1
    k_bnrelu01<<<dim3(1024, 1, 2), 256>>>(g5a, b5a, g5c, b5c);

    // PAM branch
    k_qkv<<<dim3(32, BB), 256>>>(Wq, bq, Wk, bk, Wv, bv);
    k_rowstats<<<dim3(256, BB), dim3(32, 8)>>>();
    k_pamout<<<dim3(16, BB), 256>>>(gpam);
    k_conv3<<<dim3(16, BB), 256>>>(8, W51, 2, 2);            // + BN stats slot 2
    k_bnrelu<<<1024, 256>>>(2, 6, g51, b51, 2);
    k_out1x1<<<dim3(32, 2, BB), 256>>>(6, W6, b6, out + BB * OCH);

    // CAM branch
    k_came<<<dim3(BB, 16), 256>>>();
    k_camout<<<dim3(32, BB), 256>>>(gcam);                   // softmax folded in
    k_conv3<<<dim3(16, BB), 256>>>(9, W52, 3, 3);            // + BN stats slot 3
    k_bnrelu<<<1024, 256>>>(3, 7, g52, b52, 3);
    k_out1x1<<<dim3(32, 2, BB), 256>>>(7, W7, b7, out + BB * OCH + OUTSZ);

    // fused mean path
    k_colmean<<<BB * IC, 128>>>();
    k_sasc<<<BB, OCH>>>(W8, b8, out);
}

// round 12
// speedup vs baseline: 1.4588x; 1.3073x over previous
#include <cuda_runtime.h>
#include <math.h>

#define BB   8
#define CIN  256
#define LIN  2046
#define LPAD 2048
#define IC   64
#define OCH  128
#define BNEPS 1e-5f
#define MT   32

typedef unsigned long long u64;
__device__ __forceinline__ u64 pk2(float x, float y) { u64 r; asm("mov.b64 %0,{%1,%2};" : "=l"(r) : "f"(x), "f"(y)); return r; }
__device__ __forceinline__ float2 up2(u64 v) { float2 r; asm("mov.b64 {%0,%1},%2;" : "=f"(r.x), "=f"(r.y) : "l"(v)); return r; }
__device__ __forceinline__ void fma2(u64& d, u64 a, u64 b) { asm("fma.rn.f32x2 %0,%1,%2,%0;" : "+l"(d) : "l"(a), "l"(b)); }

// ---------------- scratch ----------------
__device__ float g_pre1[BB*IC*LPAD];
__device__ float g_pre2[BB*IC*LPAD];
__device__ float g_preA[BB*IC*LPAD];
__device__ float g_preB[BB*IC*LPAD];
__device__ float g_feat1[BB*IC*LPAD];
__device__ float g_feat2[BB*IC*LPAD];
__device__ float g_saconv[BB*IC*LPAD];
__device__ float g_scconv[BB*IC*LPAD];
__device__ float g_safeat[BB*IC*LPAD];
__device__ float g_scfeat[BB*IC*LPAD];
__device__ float g_qk[BB*LPAD*16];
__device__ float g_v[BB*IC*LPAD];
__device__ float g_came[BB*IC*IC];
__device__ float g_msum[BB*IC];
__device__ float g_sS[4*IC];
__device__ float g_sSS[4*IC];
__device__ unsigned g_kmax[BB*8];

__device__ __forceinline__ float* selbuf(int s) {
    switch (s) {
        case 0: return g_pre1;   case 1: return g_pre2;
        case 2: return g_preA;   case 3: return g_preB;
        case 4: return g_feat1;  case 5: return g_feat2;
        case 6: return g_saconv; case 7: return g_scconv;
        case 8: return g_safeat; default: return g_scfeat;
    }
}

__global__ void k_zeroall() {
    int idx = blockIdx.x * 256 + threadIdx.x;
    if (idx < BB*IC*IC) g_came[idx] = 0.f;
    if (idx < 4*IC) { g_sS[idx] = 0.f; g_sSS[idx] = 0.f; }
    if (idx < BB*8) g_kmax[idx] = 0u;
}

// ---------- conv1x1 from x (256 -> 128 outs), write at l+1, fused BN stats ----------
__global__ __launch_bounds__(256) void k_convx(const float* __restrict__ x,
                                               const float* __restrict__ W5a,
                                               const float* __restrict__ W5c) {
    int b = blockIdx.z, o0 = blockIdx.y * 64, l0 = blockIdx.x * 64;
    __shared__ float Ws[16][68], Xs[16][68];
    int tid = threadIdx.x, ty = tid / 16, tx = tid % 16;
    u64 acc[4][2] = {};
    const float* xb = x + (size_t)b * CIN * LIN;
    for (int kc = 0; kc < CIN; kc += 16) {
#pragma unroll
        for (int t = 0; t < 4; t++) {
            int i = tid + t * 256, k = i / 64, o = i % 64;
            int oo = o0 + o;
            const float* Wp = (oo < IC) ? (W5a + oo * CIN) : (W5c + (oo - IC) * CIN);
            Ws[k][o] = Wp[kc + k];
        }
#pragma unroll
        for (int t = 0; t < 4; t++) {
            int i = tid + t * 256, k = i / 64, l = i % 64;
            int gl = l0 + l;
            Xs[k][l] = (gl < LIN) ? xb[(size_t)(kc + k) * LIN + gl] : 0.f;
        }
        __syncthreads();
#pragma unroll
        for (int k = 0; k < 16; k++) {
            float4 a = *(float4*)&Ws[k][ty * 4];
            u64 b01 = *(u64*)&Xs[k][tx * 4];
            u64 b23 = *(u64*)&Xs[k][tx * 4 + 2];
            u64 a0 = pk2(a.x, a.x), a1 = pk2(a.y, a.y), a2 = pk2(a.z, a.z), a3 = pk2(a.w, a.w);
            fma2(acc[0][0], a0, b01); fma2(acc[0][1], a0, b23);
            fma2(acc[1][0], a1, b01); fma2(acc[1][1], a1, b23);
            fma2(acc[2][0], a2, b01); fma2(acc[2][1], a2, b23);
            fma2(acc[3][0], a3, b01); fma2(acc[3][1], a3, b23);
        }
        __syncthreads();
    }
    int slot = blockIdx.y;
#pragma unroll
    for (int i = 0; i < 4; i++) {
        int o = o0 + ty * 4 + i;
        float* dst = (o < IC) ? (g_pre1 + ((size_t)b * IC + o) * LPAD)
                              : (g_pre2 + ((size_t)b * IC + (o - IC)) * LPAD);
        float2 p0 = up2(acc[i][0]), p1 = up2(acc[i][1]);
        float vv[4] = {p0.x, p0.y, p1.x, p1.y};
        float s = 0.f, ss = 0.f;
#pragma unroll
        for (int j = 0; j < 4; j++) {
            int l = l0 + tx * 4 + j;
            if (l < LIN) { dst[l + 1] = vv[j]; s += vv[j]; ss += vv[j] * vv[j]; }
        }
#pragma unroll
        for (int off = 8; off > 0; off >>= 1) {
            s  += __shfl_xor_sync(0xffffffffu, s, off);
            ss += __shfl_xor_sync(0xffffffffu, ss, off);
        }
        if (tx == 0) {
            int ch = (o < IC) ? o : (o - IC);
            atomicAdd(&g_sS[slot * IC + ch], s);
            atomicAdd(&g_sSS[slot * IC + ch], ss);
        }
    }
}

// ---------- BN + ReLU (float4), dual-slot via grid.z ----------
__global__ void k_bnrelu01(const float* __restrict__ g0, const float* __restrict__ bia0,
                           const float* __restrict__ g1, const float* __restrict__ bia1) {
    int z = blockIdx.z;
    const float4* pre = (const float4*)selbuf(z);
    float4* out = (float4*)selbuf(4 + z);
    const float* g = z ? g1 : g0;
    const float* bia = z ? bia1 : bia0;
    int idx = blockIdx.x * 256 + threadIdx.x;
    int l4 = idx & 511;
    int c = (idx >> 9) & (IC - 1);
    float4 v = pre[idx];
    if (l4 == 0) v.x = 0.f;
    if (l4 == 511) v.w = 0.f;
    float N = (float)(BB * LPAD);
    float mu = g_sS[z * IC + c] / N;
    float rs = rsqrtf(g_sSS[z * IC + c] / N - mu * mu + BNEPS);
    float sc = rs * g[c], sb = bia[c] - mu * sc;
    float4 r;
    r.x = fmaxf(v.x * sc + sb, 0.f); r.y = fmaxf(v.y * sc + sb, 0.f);
    r.z = fmaxf(v.z * sc + sb, 0.f); r.w = fmaxf(v.w * sc + sb, 0.f);
    out[idx] = r;
}

__global__ void k_bnrelu(int psel, int osel, const float* __restrict__ g,
                         const float* __restrict__ bia, int slot) {
    const float4* pre = (const float4*)selbuf(psel);
    float4* out = (float4*)selbuf(osel);
    int idx = blockIdx.x * 256 + threadIdx.x;
    int c = (idx >> 9) & (IC - 1);
    float4 v = pre[idx];
    float N = (float)(BB * LPAD);
    float mu = g_sS[slot * IC + c] / N;
    float rs = rsqrtf(g_sSS[slot * IC + c] / N - mu * mu + BNEPS);
    float sc = rs * g[c], sb = bia[c] - mu * sc;
    float4 r;
    r.x = fmaxf(v.x * sc + sb, 0.f); r.y = fmaxf(v.y * sc + sb, 0.f);
    r.z = fmaxf(v.z * sc + sb, 0.f); r.w = fmaxf(v.w * sc + sb, 0.f);
    out[idx] = r;
}

// ---------- q/k/v from feat1: register-tiled GEMM 80x128 per block ----------
__global__ __launch_bounds__(256) void k_qkv(const float* __restrict__ Wq, const float* __restrict__ bq,
                                             const float* __restrict__ Wk, const float* __restrict__ bk,
                                             const float* __restrict__ Wv, const float* __restrict__ bvw) {
    int b = blockIdx.y, l0 = blockIdx.x * 128;
    __shared__ float Ws[16][84], Xs[16][132];
    int tid = threadIdx.x, ty = tid / 16, tx = tid % 16;   // o=ty*5.., l=tx*8..
    u64 acc[5][4] = {};
    const float* f1 = g_feat1 + (size_t)b * IC * LPAD;
    for (int kc = 0; kc < 64; kc += 16) {
#pragma unroll
        for (int t = 0; t < 5; t++) {
            int i = tid + t * 256;              // 0..1279
            int k = i / 80, o = i % 80;
            float v;
            if (o < 8)       v = Wq[o * IC + kc + k];
            else if (o < 16) v = Wk[(o - 8) * IC + kc + k];
            else             v = Wv[(o - 16) * IC + kc + k];
            Ws[k][o] = v;
        }
#pragma unroll
        for (int t = 0; t < 2; t++) {
            int i = tid + t * 256;              // float4 idx 0..511
            int k = i / 32, l4 = (i % 32) * 4;
            float4 v = *(const float4*)(f1 + (size_t)(kc + k) * LPAD + l0 + l4);
            Xs[k][l4] = v.x; Xs[k][l4 + 1] = v.y; Xs[k][l4 + 2] = v.z; Xs[k][l4 + 3] = v.w;
        }
        __syncthreads();
#pragma unroll
        for (int k = 0; k < 16; k++) {
            u64 b0 = *(u64*)&Xs[k][tx * 8];
            u64 b1 = *(u64*)&Xs[k][tx * 8 + 2];
            u64 b2 = *(u64*)&Xs[k][tx * 8 + 4];
            u64 b3 = *(u64*)&Xs[k][tx * 8 + 6];
#pragma unroll
            for (int i = 0; i < 5; i++) {
                float a = Ws[k][ty * 5 + i];
                u64 ap = pk2(a, a);
                fma2(acc[i][0], ap, b0); fma2(acc[i][1], ap, b1);
                fma2(acc[i][2], ap, b2); fma2(acc[i][3], ap, b3);
            }
        }
        __syncthreads();
    }
#pragma unroll
    for (int i = 0; i < 5; i++) {
        int o = ty * 5 + i;
        float bias = (o < 8) ? bq[o] : ((o < 16) ? bk[o - 8] : bvw[o - 16]);
        float vv[8];
#pragma unroll
        for (int j = 0; j < 4; j++) {
            float2 p = up2(acc[i][j]);
            vv[2 * j] = p.x + bias; vv[2 * j + 1] = p.y + bias;
        }
        if (o < 16) {
#pragma unroll
            for (int j = 0; j < 8; j++)
                g_qk[((size_t)b * LPAD + l0 + tx * 8 + j) * 16 + o] = vv[j];
            if (o >= 8) {
                float ka = 0.f;
#pragma unroll
                for (int j = 0; j < 8; j++) ka = fmaxf(ka, fabsf(vv[j]));
                atomicMax(&g_kmax[b * 8 + (o - 8)], __float_as_uint(ka));
            }
        } else {
            float* dst = g_v + ((size_t)b * IC + (o - 16)) * LPAD + l0 + tx * 8;
            float4 r0 = {vv[0], vv[1], vv[2], vv[3]};
            float4 r1 = {vv[4], vv[5], vv[6], vv[7]};
            *(float4*)dst = r0; *(float4*)(dst + 4) = r1;
        }
    }
}

// ---------- PAM fused (flash-style, fixed upper-bound max) ----------
__global__ __launch_bounds__(256) void k_pamout(const float* __restrict__ gamma) {
    int b = blockIdx.y, l0 = blockIdx.x * 128;   // grid (16, 8)
    __shared__ u64  ksp[4][36];
    __shared__ float psT[MT][132];
    __shared__ float vsmT[MT][68];
    __shared__ float sumP[2][128];
    int tid = threadIdx.x;
    int lq = tid & 127, mh = tid >> 7;
    const float4* qp4 = (const float4*)(g_qk + ((size_t)b * LPAD + l0 + lq) * 16);
    float4 q0 = qp4[0], q1 = qp4[1];
    u64 qp[4] = { pk2(q0.x, q0.y), pk2(q0.z, q0.w), pk2(q1.x, q1.y), pk2(q1.z, q1.w) };
    // safe upper bound on row max
    float Mv = fabsf(q0.x) * __uint_as_float(g_kmax[b * 8 + 0])
             + fabsf(q0.y) * __uint_as_float(g_kmax[b * 8 + 1])
             + fabsf(q0.z) * __uint_as_float(g_kmax[b * 8 + 2])
             + fabsf(q0.w) * __uint_as_float(g_kmax[b * 8 + 3])
             + fabsf(q1.x) * __uint_as_float(g_kmax[b * 8 + 4])
             + fabsf(q1.y) * __uint_as_float(g_kmax[b * 8 + 5])
             + fabsf(q1.z) * __uint_as_float(g_kmax[b * 8 + 6])
             + fabsf(q1.w) * __uint_as_float(g_kmax[b * 8 + 7]);
    float lsum = 0.f;
    int cy = (tid >> 5) * 8, lx = (tid & 31) * 4;
    u64 acc[8][2] = {};
    const float* vb = g_v + (size_t)b * IC * LPAD;
    for (int m0 = 0; m0 < LPAD; m0 += MT) {
        if (tid < 128) {
            int p = tid >> 5, m = tid & 31;
            float2 kv = *(const float2*)(g_qk + ((size_t)b * LPAD + m0 + m) * 16 + 8 + 2 * p);
            ksp[p][m] = pk2(kv.x, kv.y);
        }
#pragma unroll
        for (int t = 0; t < 2; t++) {
            int i = tid + t * 256;
            int c = i >> 3, m4 = (i & 7) * 4;
            float4 v = *(const float4*)(vb + (size_t)c * LPAD + m0 + m4);
            vsmT[m4 + 0][c] = v.x; vsmT[m4 + 1][c] = v.y;
            vsmT[m4 + 2][c] = v.z; vsmT[m4 + 3][c] = v.w;
        }
        __syncthreads();
#pragma unroll
        for (int t = 0; t < 16; t++) {
            int m = mh * 16 + t;
            u64 s2 = 0ull;
            fma2(s2, qp[0], ksp[0][m]); fma2(s2, qp[1], ksp[1][m]);
            fma2(s2, qp[2], ksp[2][m]); fma2(s2, qp[3], ksp[3][m]);
            float2 sv = up2(s2);
            float p = __expf(sv.x + sv.y - Mv);
            psT[m][lq] = p;
            lsum += p;
        }
        __syncthreads();
#pragma unroll 4
        for (int m = 0; m < MT; m++) {
            u64 p01 = *(u64*)&psT[m][lx];
            u64 p23 = *(u64*)&psT[m][lx + 2];
            float4 v0 = *(float4*)&vsmT[m][cy];
            float4 v1 = *(float4*)&vsmT[m][cy + 4];
            u64 d0 = pk2(v0.x, v0.x), d1 = pk2(v0.y, v0.y), d2 = pk2(v0.z, v0.z), d3 = pk2(v0.w, v0.w);
            u64 d4 = pk2(v1.x, v1.x), d5 = pk2(v1.y, v1.y), d6 = pk2(v1.z, v1.z), d7 = pk2(v1.w, v1.w);
            fma2(acc[0][0], d0, p01); fma2(acc[0][1], d0, p23);
            fma2(acc[1][0], d1, p01); fma2(acc[1][1], d1, p23);
            fma2(acc[2][0], d2, p01); fma2(acc[2][1], d2, p23);
            fma2(acc[3][0], d3, p01); fma2(acc[3][1], d3, p23);
            fma2(acc[4][0], d4, p01); fma2(acc[4][1], d4, p23);
            fma2(acc[5][0], d5, p01); fma2(acc[5][1], d5, p23);
            fma2(acc[6][0], d6, p01); fma2(acc[6][1], d6, p23);
            fma2(acc[7][0], d7, p01); fma2(acc[7][1], d7, p23);
        }
        __syncthreads();
    }
    sumP[mh][lq] = lsum;
    __syncthreads();
    float i0 = 1.f / (sumP[0][lx + 0] + sumP[1][lx + 0]);
    float i1 = 1.f / (sumP[0][lx + 1] + sumP[1][lx + 1]);
    float i2 = 1.f / (sumP[0][lx + 2] + sumP[1][lx + 2]);
    float i3 = 1.f / (sumP[0][lx + 3] + sumP[1][lx + 3]);
    float gm = gamma[0];
#pragma unroll
    for (int i = 0; i < 8; i++) {
        size_t row = ((size_t)b * IC + cy + i) * LPAD + l0 + lx;
        float2 a0 = up2(acc[i][0]), a1 = up2(acc[i][1]);
        float4 f = *(const float4*)(g_feat1 + row);
        float4 r;
        r.x = gm * a0.x * i0 + f.x; r.y = gm * a0.y * i1 + f.y;
        r.z = gm * a1.x * i2 + f.z; r.w = gm * a1.y * i3 + f.w;
        *(float4*)(g_safeat + row) = r;
    }
}

// ---------- CAM energy ----------
__global__ __launch_bounds__(256) void k_came() {
    int b = blockIdx.x, ls = blockIdx.y;
    __shared__ float Fs[64][33];
    int tid = threadIdx.x;
    int cy = (tid / 16) * 4, dx = (tid % 16) * 4;
    float acc[4][4] = {};
    const float* f2 = g_feat2 + (size_t)b * IC * LPAD;
    for (int lt = 0; lt < 4; lt++) {
        int l0 = ls * 128 + lt * 32;
        for (int i = tid; i < 512; i += 256) {
            int c = i / 8, w = (i % 8) * 4;
            float4 v = *(const float4*)(f2 + (size_t)c * LPAD + l0 + w);
            Fs[c][w] = v.x; Fs[c][w + 1] = v.y; Fs[c][w + 2] = v.z; Fs[c][w + 3] = v.w;
        }
        __syncthreads();
#pragma unroll 8
        for (int j = 0; j < 32; j++) {
            float a[4], bv[4];
#pragma unroll
            for (int i = 0; i < 4; i++) a[i] = Fs[cy + i][j];
#pragma unroll
            for (int i = 0; i < 4; i++) bv[i] = Fs[dx + i][j];
#pragma unroll
            for (int i = 0; i < 4; i++)
#pragma unroll
                for (int jj = 0; jj < 4; jj++) acc[i][jj] += a[i] * bv[jj];
        }
        __syncthreads();
    }
#pragma unroll
    for (int i = 0; i < 4; i++)
#pragma unroll
        for (int jj = 0; jj < 4; jj++)
            atomicAdd(&g_came[b * 4096 + (cy + i) * 64 + dx + jj], acc[i][jj]);
}

// ---------- CAM: softmax (folded) + out GEMM + epilogue ----------
__global__ __launch_bounds__(256) void k_camout(const float* __restrict__ gamma) {
    int b = blockIdx.y, l0 = blockIdx.x * 64;
    __shared__ float As[64][65], Fs[64][68];
    int tid = threadIdx.x;
    const float* f2 = g_feat2 + (size_t)b * IC * LPAD;
    for (int i = tid; i < 4096; i += 256) As[i / 64][i % 64] = g_came[b * 4096 + i];
    for (int i = tid; i < 1024; i += 256) {
        int d = i / 16, w = (i % 16) * 4;
        float4 v = *(const float4*)(f2 + (size_t)d * LPAD + l0 + w);
        Fs[d][w] = v.x; Fs[d][w + 1] = v.y; Fs[d][w + 2] = v.z; Fs[d][w + 3] = v.w;
    }
    __syncthreads();
    {
        int r = tid / 4, q = tid % 4;
        float e[16];
        float mn = 1e30f;
#pragma unroll
        for (int k = 0; k < 16; k++) { e[k] = As[r][q * 16 + k]; mn = fminf(mn, e[k]); }
        mn = fminf(mn, __shfl_xor_sync(0xffffffffu, mn, 1));
        mn = fminf(mn, __shfl_xor_sync(0xffffffffu, mn, 2));
        float s = 0.f;
#pragma unroll
        for (int k = 0; k < 16; k++) { e[k] = __expf(mn - e[k]); s += e[k]; }
        s += __shfl_xor_sync(0xffffffffu, s, 1);
        s += __shfl_xor_sync(0xffffffffu, s, 2);
        float inv = 1.f / s;
#pragma unroll
        for (int k = 0; k < 16; k++) As[r][q * 16 + k] = e[k] * inv;
    }
    __syncthreads();
    int cy = (tid / 16) * 4, lx = (tid % 16) * 4;
    u64 acc[4][2] = {};
#pragma unroll 4
    for (int d = 0; d < 64; d++) {
        u64 b01 = *(u64*)&Fs[d][lx];
        u64 b23 = *(u64*)&Fs[d][lx + 2];
#pragma unroll
        for (int i = 0; i < 4; i++) {
            float a = As[cy + i][d];
            u64 ap = pk2(a, a);
            fma2(acc[i][0], ap, b01);
            fma2(acc[i][1], ap, b23);
        }
    }
    float gm = gamma[0];
#pragma unroll
    for (int i = 0; i < 4; i++) {
        size_t row = ((size_t)b * IC + cy + i) * LPAD + l0 + lx;
        float2 a0 = up2(acc[i][0]), a1 = up2(acc[i][1]);
        float4 f = *(const float4*)(f2 + (size_t)(cy + i) * LPAD + l0 + lx);
        float4 r;
        r.x = gm * a0.x + f.x; r.y = gm * a0.y + f.y;
        r.z = gm * a1.x + f.z; r.w = gm * a1.y + f.w;
        *(float4*)(g_scfeat + row) = r;
    }
}

// ---------- conv3 pad1 (64 -> 64), f32x2, fused BN stats ----------
__global__ __launch_bounds__(256) void k_conv3(int fsel, const float* __restrict__ W, int osel, int slot) {
    const float* f = selbuf(fsel);
    float* out = selbuf(osel);
    int b = blockIdx.y, l0 = blockIdx.x * 128;
    __shared__ float Fs[16][134], Ws2[16][194];
    int tid = threadIdx.x;
    int og = tid / 32, lg = tid % 32;
    u64 acc[8][2] = {};
    const float* fb = f + (size_t)b * IC * LPAD;
    for (int c0 = 0; c0 < 64; c0 += 16) {
        for (int i = tid; i < 2080; i += 256) {
            int cc = i / 130, j = i % 130;
            int gl = l0 + j - 1;
            Fs[cc][j] = (gl >= 0 && gl < LPAD) ? fb[(size_t)(c0 + cc) * LPAD + gl] : 0.f;
        }
        for (int i = tid; i < 3072; i += 256) {
            int o = i / 48, r = i % 48;
            Ws2[r / 3][o * 3 + (r % 3)] = W[o * 192 + c0 * 3 + r];
        }
        __syncthreads();
#pragma unroll
        for (int cc = 0; cc < 16; cc++) {
            float bv[6];
#pragma unroll
            for (int j = 0; j < 6; j++) bv[j] = Fs[cc][lg * 4 + j];
            u64 A = pk2(bv[0], bv[1]), Bp = pk2(bv[1], bv[2]), C = pk2(bv[2], bv[3]);
            u64 D = pk2(bv[3], bv[4]), E = pk2(bv[4], bv[5]);
#pragma unroll
            for (int oi = 0; oi < 8; oi++) {
                int o = og * 8 + oi;
                float w0 = Ws2[cc][o * 3], w1 = Ws2[cc][o * 3 + 1], w2 = Ws2[cc][o * 3 + 2];
                u64 w0d = pk2(w0, w0), w1d = pk2(w1, w1), w2d = pk2(w2, w2);
                fma2(acc[oi][0], w0d, A); fma2(acc[oi][0], w1d, Bp); fma2(acc[oi][0], w2d, C);
                fma2(acc[oi][1], w0d, C); fma2(acc[oi][1], w1d, D);  fma2(acc[oi][1], w2d, E);
            }
        }
        __syncthreads();
    }
#pragma unroll
    for (int oi = 0; oi < 8; oi++) {
        float2 x0 = up2(acc[oi][0]), x1 = up2(acc[oi][1]);
        float4 r; r.x = x0.x; r.y = x0.y; r.z = x1.x; r.w = x1.y;
        *(float4*)(out + ((size_t)b * IC + og * 8 + oi) * LPAD + l0 + lg * 4) = r;
        float s = r.x + r.y + r.z + r.w;
        float ss = r.x * r.x + r.y * r.y + r.z * r.z + r.w * r.w;
#pragma unroll
        for (int off = 16; off > 0; off >>= 1) {
            s  += __shfl_xor_sync(0xffffffffu, s, off);
            ss += __shfl_xor_sync(0xffffffffu, ss, off);
        }
        if (lg == 0) {
            atomicAdd(&g_sS[slot * IC + og * 8 + oi], s);
            atomicAdd(&g_sSS[slot * IC + og * 8 + oi], ss);
        }
    }
}

// ---------- final 1x1 conv 64 -> 128 ----------
__global__ __launch_bounds__(256) void k_out1x1(int ssel, const float* __restrict__ W,
                                                const float* __restrict__ bias,
                                                float* __restrict__ dst) {
    const float* src = selbuf(ssel);
    int b = blockIdx.z, o0 = blockIdx.y * 64, l0 = blockIdx.x * 64;
    __shared__ float Ws[16][68], Xs[16][68];
    int tid = threadIdx.x, ty = tid / 16, tx = tid % 16;
    u64 acc[4][2] = {};
    const float* sb = src + (size_t)b * IC * LPAD;
    for (int kc = 0; kc < 64; kc += 16) {
#pragma unroll
        for (int t = 0; t < 4; t++) {
            int i = tid + t * 256, k = i / 64, o = i % 64;
            Ws[k][o] = W[(o0 + o) * 64 + kc + k];
        }
#pragma unroll
        for (int t = 0; t < 4; t++) {
            int i = tid + t * 256, k = i / 64, l = i % 64;
            Xs[k][l] = sb[(size_t)(kc + k) * LPAD + l0 + l];
        }
        __syncthreads();
#pragma unroll
        for (int k = 0; k < 16; k++) {
            float4 a = *(float4*)&Ws[k][ty * 4];
            u64 b01 = *(u64*)&Xs[k][tx * 4];
            u64 b23 = *(u64*)&Xs[k][tx * 4 + 2];
            u64 a0 = pk2(a.x, a.x), a1 = pk2(a.y, a.y), a2 = pk2(a.z, a.z), a3 = pk2(a.w, a.w);
            fma2(acc[0][0], a0, b01); fma2(acc[0][1], a0, b23);
            fma2(acc[1][0], a1, b01); fma2(acc[1][1], a1, b23);
            fma2(acc[2][0], a2, b01); fma2(acc[2][1], a2, b23);
            fma2(acc[3][0], a3, b01); fma2(acc[3][1], a3, b23);
        }
        __syncthreads();
    }
#pragma unroll
    for (int i = 0; i < 4; i++) {
        int o = o0 + ty * 4 + i;
        float bs = bias[o];
        float2 p0 = up2(acc[i][0]), p1 = up2(acc[i][1]);
        float4 r; r.x = p0.x + bs; r.y = p0.y + bs; r.z = p1.x + bs; r.w = p1.y + bs;
        *(float4*)(dst + ((size_t)b * OCH + o) * LPAD + l0 + tx * 4) = r;
    }
}

// ---------- column mean of (saconv + scconv) ----------
__global__ void k_colmean() {
    int b = blockIdx.x / IC, c = blockIdx.x % IC;
    const float4* p1 = (const float4*)(g_saconv + ((size_t)b * IC + c) * LPAD);
    const float4* p2 = (const float4*)(g_scconv + ((size_t)b * IC + c) * LPAD);
    float s = 0.f;
    for (int l = threadIdx.x; l < LPAD / 4; l += 128) {
        float4 a = p1[l], bq = p2[l];
        s += a.x + a.y + a.z + a.w + bq.x + bq.y + bq.z + bq.w;
    }
#pragma unroll
    for (int off = 16; off > 0; off >>= 1) s += __shfl_xor_sync(0xffffffffu, s, off);
    __shared__ float red[4];
    int lane = threadIdx.x & 31, wid = threadIdx.x >> 5;
    if (lane == 0) red[wid] = s;
    __syncthreads();
    if (threadIdx.x == 0)
        g_msum[b * IC + c] = (red[0] + red[1] + red[2] + red[3]) / (float)LPAD;
}

__global__ void k_sasc(const float* __restrict__ W8, const float* __restrict__ b8,
                       float* __restrict__ dout) {
    int b = blockIdx.x, o = threadIdx.x;
    float s = b8[o];
    for (int c = 0; c < IC; c++) s += W8[o * IC + c] * g_msum[b * IC + c];
    dout[b * OCH + o] = s;
}

extern "C" void kernel_launch(void* const* d_in, const int* in_sizes, int n_in,
                              void* d_out, int out_size) {
    const float* x   = (const float*)d_in[0];
    const float* W5a = (const float*)d_in[1];
    const float* g5a = (const float*)d_in[2];
    const float* b5a = (const float*)d_in[3];
    const float* W5c = (const float*)d_in[4];
    const float* g5c = (const float*)d_in[5];
    const float* b5c = (const float*)d_in[6];
    const float* Wq  = (const float*)d_in[7];
    const float* bq  = (const float*)d_in[8];
    const float* Wk  = (const float*)d_in[9];
    const float* bk  = (const float*)d_in[10];
    const float* Wv  = (const float*)d_in[11];
    const float* bv  = (const float*)d_in[12];
    const float* gpam = (const float*)d_in[13];
    const float* gcam = (const float*)d_in[14];
    const float* W51 = (const float*)d_in[15];
    const float* g51 = (const float*)d_in[16];
    const float* b51 = (const float*)d_in[17];
    const float* W52 = (const float*)d_in[18];
    const float* g52 = (const float*)d_in[19];
    const float* b52 = (const float*)d_in[20];
    const float* W6  = (const float*)d_in[21];
    const float* b6  = (const float*)d_in[22];
    const float* W7  = (const float*)d_in[23];
    const float* b7  = (const float*)d_in[24];
    const float* W8  = (const float*)d_in[25];
    const float* b8  = (const float*)d_in[26];
    float* out = (float*)d_out;
    const size_t OUTSZ = (size_t)BB * OCH * LPAD;

    k_zeroall<<<131, 256>>>();
    k_convx<<<dim3(32, 2, BB), 256>>>(x, W5a, W5c);
    k_bnrelu01<<<dim3(1024, 1, 2), 256>>>(g5a, b5a, g5c, b5c);

    // PAM branch
    k_qkv<<<dim3(16, BB), 256>>>(Wq, bq, Wk, bk, Wv, bv);
    k_pamout<<<dim3(16, BB), 256>>>(gpam);
    k_conv3<<<dim3(16, BB), 256>>>(8, W51, 2, 2);
    k_bnrelu<<<1024, 256>>>(2, 6, g51, b51, 2);
    k_out1x1<<<dim3(32, 2, BB), 256>>>(6, W6, b6, out + BB * OCH);

    // CAM branch
    k_came<<<dim3(BB, 16), 256>>>();
    k_camout<<<dim3(32, BB), 256>>>(gcam);
    k_conv3<<<dim3(16, BB), 256>>>(9, W52, 3, 3);
    k_bnrelu<<<1024, 256>>>(3, 7, g52, b52, 3);
    k_out1x1<<<dim3(32, 2, BB), 256>>>(7, W7, b7, out + BB * OCH + OUTSZ);

    // fused mean path
    k_colmean<<<BB * IC, 128>>>();
    k_sasc<<<BB, OCH>>>(W8, b8, out);
}